// round 1
// baseline (speedup 1.0000x reference)
#include <cuda_runtime.h>
#include <math.h>

// Problem constants
#define B_   2
#define T_   2048
#define DIM_ 2048
#define H_   32
#define HKV_ 8
#define HD_  64
#define NREP_ 4
#define M_   (B_ * T_)            // 4096
#define KVD_ (HKV_ * HD_)         // 512

// ---------------------------------------------------------------------------
// Scratch (no allocations allowed -> device globals)
// ---------------------------------------------------------------------------
__device__ float g_q[(size_t)M_ * DIM_];      // 32 MB
__device__ float g_k[(size_t)M_ * KVD_];      // 8 MB
__device__ float g_v[(size_t)M_ * KVD_];      // 8 MB
__device__ float g_att[(size_t)M_ * DIM_];    // 32 MB

// ---------------------------------------------------------------------------
// SGEMM: C[M,N] = A[M,K] @ B[K,N], all row-major, fp32.
// 128x128 block tile, BK=8, 8x8 per thread, 256 threads.
// All dims are multiples of the tile sizes here (no bounds checks).
// ---------------------------------------------------------------------------
__device__ __forceinline__ void sgemm_body(const float* __restrict__ A,
                                           const float* __restrict__ Bm,
                                           float* __restrict__ C,
                                           int N, int K, int mb, int cb) {
    __shared__ float As[8][128];
    __shared__ float Bs[8][128];

    const int tid = threadIdx.x;
    const int tx  = tid % 16;   // col group (8 cols each)
    const int ty  = tid / 16;   // row group (8 rows each)

    const float* Ab = A + (size_t)mb * 128 * K;
    const float* Bb = Bm + (size_t)cb * 128;

    const int arow = tid >> 1;          // 0..127
    const int acol = (tid & 1) * 4;     // 0 or 4
    const int brow = tid >> 5;          // 0..7
    const int bcol = (tid & 31) * 4;    // 0..124

    float acc[8][8];
#pragma unroll
    for (int i = 0; i < 8; i++)
#pragma unroll
        for (int j = 0; j < 8; j++) acc[i][j] = 0.f;

    for (int k0 = 0; k0 < K; k0 += 8) {
        float4 av = *(const float4*)(Ab + (size_t)arow * K + k0 + acol);
        As[acol + 0][arow] = av.x;
        As[acol + 1][arow] = av.y;
        As[acol + 2][arow] = av.z;
        As[acol + 3][arow] = av.w;
        *(float4*)(&Bs[brow][bcol]) =
            *(const float4*)(Bb + (size_t)(k0 + brow) * N + bcol);
        __syncthreads();

#pragma unroll
        for (int kk = 0; kk < 8; kk++) {
            float4 a0 = *(const float4*)&As[kk][ty * 8];
            float4 a1 = *(const float4*)&As[kk][ty * 8 + 4];
            float4 b0 = *(const float4*)&Bs[kk][tx * 8];
            float4 b1 = *(const float4*)&Bs[kk][tx * 8 + 4];
            float ra[8] = {a0.x, a0.y, a0.z, a0.w, a1.x, a1.y, a1.z, a1.w};
            float rb[8] = {b0.x, b0.y, b0.z, b0.w, b1.x, b1.y, b1.z, b1.w};
#pragma unroll
            for (int i = 0; i < 8; i++)
#pragma unroll
                for (int j = 0; j < 8; j++)
                    acc[i][j] += ra[i] * rb[j];
        }
        __syncthreads();
    }

    float* Cb = C + (size_t)(mb * 128) * N + cb * 128;
#pragma unroll
    for (int i = 0; i < 8; i++) {
#pragma unroll
        for (int j = 0; j < 8; j += 4) {
            float4 v = make_float4(acc[i][j], acc[i][j + 1],
                                   acc[i][j + 2], acc[i][j + 3]);
            *(float4*)(&Cb[(size_t)(ty * 8 + i) * N + tx * 8 + j]) = v;
        }
    }
}

// Fused QKV projection: grid.x in [0,24): 0..15 -> Q cols, 16..19 -> K, 20..23 -> V
__global__ __launch_bounds__(256)
void sgemm_qkv_kernel(const float* __restrict__ x,
                      const float* __restrict__ wq,
                      const float* __restrict__ wk,
                      const float* __restrict__ wv) {
    const int xb = blockIdx.x;
    const int mb = blockIdx.y;
    const float* Bm;
    float* Cm;
    int N, cb;
    if (xb < 16)      { Bm = wq; Cm = g_q; N = DIM_; cb = xb;      }
    else if (xb < 20) { Bm = wk; Cm = g_k; N = KVD_; cb = xb - 16; }
    else              { Bm = wv; Cm = g_v; N = KVD_; cb = xb - 20; }
    sgemm_body(x, Bm, Cm, N, DIM_, mb, cb);
}

// Output projection: out = g_att @ wo
__global__ __launch_bounds__(256)
void sgemm_out_kernel(const float* __restrict__ wo, float* __restrict__ out) {
    sgemm_body(g_att, wo, out, DIM_, DIM_, blockIdx.y, blockIdx.x);
}

// ---------------------------------------------------------------------------
// RoPE (interleaved pairs), in place on g_q / g_k
// ---------------------------------------------------------------------------
__global__ void rope_q_kernel(const float* __restrict__ fc,
                              const float* __restrict__ fs) {
    int idx = blockIdx.x * blockDim.x + threadIdx.x;
    const int total = M_ * H_ * (HD_ / 2);
    if (idx >= total) return;
    int i = idx & 31;
    int h = (idx >> 5) & (H_ - 1);
    int m = idx >> 10;          // / (32*32)
    int t = m & (T_ - 1);
    float c = fc[t * 32 + i];
    float s = fs[t * 32 + i];
    float2* p = (float2*)&g_q[(size_t)m * DIM_ + h * HD_ + 2 * i];
    float2 v = *p;
    *p = make_float2(v.x * c - v.y * s, v.x * s + v.y * c);
}

__global__ void rope_k_kernel(const float* __restrict__ fc,
                              const float* __restrict__ fs) {
    int idx = blockIdx.x * blockDim.x + threadIdx.x;
    const int total = M_ * HKV_ * (HD_ / 2);
    if (idx >= total) return;
    int i = idx & 31;
    int h = (idx >> 5) & (HKV_ - 1);
    int m = idx >> 8;           // / (32*8)
    int t = m & (T_ - 1);
    float c = fc[t * 32 + i];
    float s = fs[t * 32 + i];
    float2* p = (float2*)&g_k[(size_t)m * KVD_ + h * HD_ + 2 * i];
    float2 v = *p;
    *p = make_float2(v.x * c - v.y * s, v.x * s + v.y * c);
}

// ---------------------------------------------------------------------------
// Flash-attention (causal, GQA). One block = 64 q rows of one (b,h).
// 256 threads: thread (r = tid/4, sub = tid%4); each thread owns 16 score
// columns / 16 output dims of row r. Online softmax in registers.
// Shared: Qs[64][65], Kt[64][68] (reused as P), Vs[64][68] -> 51456 B dynamic.
// ---------------------------------------------------------------------------
#define QS_LD 65
#define KS_LD 68
#define ATTN_SMEM_BYTES ((64 * QS_LD + 2 * 64 * KS_LD) * 4)

__global__ __launch_bounds__(256)
void attn_kernel() {
    extern __shared__ float sm[];
    float* Qs = sm;                    // 64 x 65
    float* Kt = sm + 64 * QS_LD;       // 64 x 68 (transposed K; reused as P)
    float* Vs = Kt + 64 * KS_LD;       // 64 x 68

    const int qt = blockIdx.x;         // q tile (0..31)
    const int h  = blockIdx.y;         // head
    const int b  = blockIdx.z;
    const int g  = h >> 2;             // kv head (NREP=4)
    const int tid = threadIdx.x;
    const int r   = tid >> 2;          // 0..63
    const int sub = tid & 3;           // 0..3
    const int qrow0 = qt * 64;

    // Load Q tile [64 x 64]
    {
        const float* qrow = g_q + ((size_t)(b * T_ + qrow0 + (tid >> 2))) * DIM_ + h * HD_;
        float* dstrow = &Qs[(tid >> 2) * QS_LD];
#pragma unroll
        for (int it = 0; it < 4; it++) {
            int ch = (tid & 3) + it * 4;      // 0..15
            float4 qv = *(const float4*)(qrow + ch * 4);
            float* d = dstrow + ch * 4;
            d[0] = qv.x; d[1] = qv.y; d[2] = qv.z; d[3] = qv.w;
        }
    }

    float o[16];
#pragma unroll
    for (int i = 0; i < 16; i++) o[i] = 0.f;
    float l = 0.f;
    float mprev = -INFINITY;
    const int iglob = qrow0 + r;

    for (int kt = 0; kt <= qt; kt++) {
        __syncthreads();   // previous iter done with Vs / P (=Kt)

        // Load K (transposed -> Kt[d][j]) and V (natural -> Vs[j][d])
        {
            const int jj = tid >> 2;
            const float* krow = g_k + ((size_t)(b * T_ + kt * 64 + jj)) * KVD_ + g * HD_;
            const float* vrow = g_v + ((size_t)(b * T_ + kt * 64 + jj)) * KVD_ + g * HD_;
#pragma unroll
            for (int it = 0; it < 4; it++) {
                int ch = (tid & 3) + it * 4;  // 0..15
                float4 kv = *(const float4*)(krow + ch * 4);
                Kt[(ch * 4 + 0) * KS_LD + jj] = kv.x;
                Kt[(ch * 4 + 1) * KS_LD + jj] = kv.y;
                Kt[(ch * 4 + 2) * KS_LD + jj] = kv.z;
                Kt[(ch * 4 + 3) * KS_LD + jj] = kv.w;
                float4 vv = *(const float4*)(vrow + ch * 4);
                *(float4*)(&Vs[jj * KS_LD + ch * 4]) = vv;
            }
        }
        __syncthreads();

        // Scores: s[i] = q_row . k_col(sub*16+i)
        float s[16];
#pragma unroll
        for (int i = 0; i < 16; i++) s[i] = 0.f;
        const float* qr = &Qs[r * QS_LD];
#pragma unroll 4
        for (int d = 0; d < 64; d++) {
            float qv = qr[d];
            const float* kd = &Kt[d * KS_LD + sub * 16];
#pragma unroll
            for (int i = 0; i < 16; i += 4) {
                float4 kv = *(const float4*)(kd + i);
                s[i]     += qv * kv.x;
                s[i + 1] += qv * kv.y;
                s[i + 2] += qv * kv.z;
                s[i + 3] += qv * kv.w;
            }
        }

        const float scale = 0.125f;   // 1/sqrt(64)
        if (kt == qt) {
#pragma unroll
            for (int i = 0; i < 16; i++) {
                int jglob = kt * 64 + sub * 16 + i;
                s[i] = (jglob <= iglob) ? s[i] * scale : -INFINITY;
            }
        } else {
#pragma unroll
            for (int i = 0; i < 16; i++) s[i] *= scale;
        }

        // Row max across this thread's 16 and the 4-thread group
        float mloc = s[0];
#pragma unroll
        for (int i = 1; i < 16; i++) mloc = fmaxf(mloc, s[i]);
        mloc = fmaxf(mloc, __shfl_xor_sync(0xffffffffu, mloc, 1));
        mloc = fmaxf(mloc, __shfl_xor_sync(0xffffffffu, mloc, 2));
        float mnew  = fmaxf(mprev, mloc);
        float alpha = __expf(mprev - mnew);

        __syncthreads();   // everyone done reading Kt before reuse as P

        float* Ps = Kt;
        float psum = 0.f;
        float* prow = &Ps[r * KS_LD + sub * 16];
#pragma unroll
        for (int i = 0; i < 16; i++) {
            float p = __expf(s[i] - mnew);
            psum += p;
            prow[i] = p;
        }
        psum += __shfl_xor_sync(0xffffffffu, psum, 1);
        psum += __shfl_xor_sync(0xffffffffu, psum, 2);
        l = l * alpha + psum;
        mprev = mnew;
#pragma unroll
        for (int i = 0; i < 16; i++) o[i] *= alpha;
        __syncwarp();      // P visibility within the 4-thread row groups

        // O += P @ V
        const float* prow_full = &Ps[r * KS_LD];
#pragma unroll 4
        for (int c = 0; c < 64; c++) {
            float pv = prow_full[c];
            const float* vd = &Vs[c * KS_LD + sub * 16];
#pragma unroll
            for (int i = 0; i < 16; i += 4) {
                float4 vv = *(const float4*)(vd + i);
                o[i]     += pv * vv.x;
                o[i + 1] += pv * vv.y;
                o[i + 2] += pv * vv.z;
                o[i + 3] += pv * vv.w;
            }
        }
    }

    // Epilogue: normalize and store to g_att[b,t, h*64 + sub*16 + i]
    float inv = 1.f / l;
    float* ob = g_att + ((size_t)(b * T_ + iglob)) * DIM_ + h * HD_ + sub * 16;
#pragma unroll
    for (int i = 0; i < 16; i += 4) {
        float4 vv = make_float4(o[i] * inv, o[i + 1] * inv,
                                o[i + 2] * inv, o[i + 3] * inv);
        *(float4*)(ob + i) = vv;
    }
}

// ---------------------------------------------------------------------------
// Launcher
// ---------------------------------------------------------------------------
extern "C" void kernel_launch(void* const* d_in, const int* in_sizes, int n_in,
                              void* d_out, int out_size) {
    const float* x  = (const float*)d_in[0];
    const float* fc = (const float*)d_in[1];
    const float* fs = (const float*)d_in[2];
    const float* wq = (const float*)d_in[3];
    const float* wk = (const float*)d_in[4];
    const float* wv = (const float*)d_in[5];
    const float* wo = (const float*)d_in[6];
    float* out = (float*)d_out;

    // 1) Fused QKV projections
    sgemm_qkv_kernel<<<dim3(24, 32), 256>>>(x, wq, wk, wv);

    // 2) RoPE on Q and K (in place)
    rope_q_kernel<<<(M_ * H_ * 32 + 255) / 256, 256>>>(fc, fs);
    rope_k_kernel<<<(M_ * HKV_ * 32 + 255) / 256, 256>>>(fc, fs);

    // 3) Causal GQA flash attention
    cudaFuncSetAttribute(attn_kernel,
                         cudaFuncAttributeMaxDynamicSharedMemorySize,
                         ATTN_SMEM_BYTES);
    attn_kernel<<<dim3(T_ / 64, H_, B_), 256, ATTN_SMEM_BYTES>>>();

    // 4) Output projection
    sgemm_out_kernel<<<dim3(16, 32), 256>>>(wo, out);
}

// round 3
// speedup vs baseline: 1.2284x; 1.2284x over previous
#include <cuda_runtime.h>
#include <cuda_bf16.h>
#include <math.h>
#include <stdint.h>

// Problem constants
#define B_   2
#define T_   2048
#define DIM_ 2048
#define H_   32
#define HKV_ 8
#define HD_  64
#define NREP_ 4
#define M_   (B_ * T_)            // 4096
#define KVD_ (HKV_ * HD_)         // 512
#define KDEPTH_ 2048

// ---------------------------------------------------------------------------
// Scratch (no allocations allowed -> device globals)
// ---------------------------------------------------------------------------
__device__ float g_q[(size_t)M_ * DIM_];      // 32 MB
__device__ float g_k[(size_t)M_ * KVD_];      // 8 MB
__device__ float g_v[(size_t)M_ * KVD_];      // 8 MB
__device__ float g_att[(size_t)M_ * DIM_];    // 32 MB

// ---------------------------------------------------------------------------
// Helpers
// ---------------------------------------------------------------------------
__device__ __forceinline__ uint32_t smem_u32(const void* p) {
    uint32_t a;
    asm("{ .reg .u64 t; cvta.to.shared.u64 t, %1; cvt.u32.u64 %0, t; }"
        : "=r"(a) : "l"(p));
    return a;
}

__device__ __forceinline__ uint32_t packbf2(__nv_bfloat16 a, __nv_bfloat16 b) {
    return ((uint32_t)__bfloat16_as_ushort(b) << 16) | (uint32_t)__bfloat16_as_ushort(a);
}

__device__ __forceinline__ void ldsm_x4(uint32_t addr, uint32_t* r) {
    asm volatile("ldmatrix.sync.aligned.m8n8.x4.shared.b16 {%0,%1,%2,%3}, [%4];"
                 : "=r"(r[0]), "=r"(r[1]), "=r"(r[2]), "=r"(r[3]) : "r"(addr));
}

__device__ __forceinline__ void mma_bf16(float* c, const uint32_t* a, const uint32_t* b) {
    asm volatile(
        "mma.sync.aligned.m16n8k16.row.col.f32.bf16.bf16.f32 "
        "{%0,%1,%2,%3}, {%4,%5,%6,%7}, {%8,%9}, {%0,%1,%2,%3};"
        : "+f"(c[0]), "+f"(c[1]), "+f"(c[2]), "+f"(c[3])
        : "r"(a[0]), "r"(a[1]), "r"(a[2]), "r"(a[3]), "r"(b[0]), "r"(b[1]));
}

// ---------------------------------------------------------------------------
// HMMA bf16 (3-term split) GEMM: C[128,128] = A[128,K] @ B[K,128]
// A row-major [Mtot,K], B row-major [K,N]. 256 threads, 8 warps (2x4 of 64x32).
// smem per stage: As[128 rows][128B] (hi cols 0..31, lo cols 32..63 bf16)
//                 Bs[128 n-rows][128B] (same split, k contiguous)
// XOR swizzle: 16B-chunk' = chunk ^ (row & 7)  -> conflict-free ldmatrix.
// Double buffered: 2 * 32KB = 64KB dynamic smem.
// ---------------------------------------------------------------------------
#define BKG 32
#define GSTAGE 32768
#define GEMM_SMEM_BYTES (2 * GSTAGE)

__device__ __forceinline__ void stage_tile(const float* __restrict__ A,
                                           const float* __restrict__ Bg,
                                           int N, int K, int m0, int n0, int k0,
                                           char* As, char* Bs, int tid) {
    // ---- A: 128 rows x 32 k (1024 float4, 4 per thread) ----
#pragma unroll
    for (int it = 0; it < 4; it++) {
        int idx = it * 256 + tid;
        int r  = idx >> 3;
        int c4 = idx & 7;                 // float4 index within row (k = c4*4)
        float4 v = *(const float4*)(A + (size_t)(m0 + r) * K + k0 + c4 * 4);
        __nv_bfloat16 hx = __float2bfloat16_rn(v.x);
        __nv_bfloat16 hy = __float2bfloat16_rn(v.y);
        __nv_bfloat16 hz = __float2bfloat16_rn(v.z);
        __nv_bfloat16 hw = __float2bfloat16_rn(v.w);
        __nv_bfloat16 lx = __float2bfloat16_rn(v.x - __bfloat162float(hx));
        __nv_bfloat16 ly = __float2bfloat16_rn(v.y - __bfloat162float(hy));
        __nv_bfloat16 lz = __float2bfloat16_rn(v.z - __bfloat162float(hz));
        __nv_bfloat16 lw = __float2bfloat16_rn(v.w - __bfloat162float(hw));
        int chunk_h = c4 >> 1;            // 0..3
        int sub     = (c4 & 1) * 8;
        uint32_t off_h = (uint32_t)r * 128 + (uint32_t)((chunk_h ^ (r & 7)) << 4) + sub;
        uint32_t off_l = (uint32_t)r * 128 + (uint32_t)(((chunk_h + 4) ^ (r & 7)) << 4) + sub;
        *(uint2*)(As + off_h) = make_uint2(packbf2(hx, hy), packbf2(hz, hw));
        *(uint2*)(As + off_l) = make_uint2(packbf2(lx, ly), packbf2(lz, lw));
    }
    // ---- B transposed: Bs[n][k], 128 n x 32 k ----
#pragma unroll
    for (int it = 0; it < 4; it++) {
        int idx = it * 256 + tid;
        int n = idx & 127;
        int g = idx >> 7;                 // k group of 4: k = g*4
        const float* bp = Bg + (size_t)(k0 + g * 4) * N + n0 + n;
        float b0 = bp[0];
        float b1 = bp[(size_t)N];
        float b2 = bp[(size_t)2 * N];
        float b3 = bp[(size_t)3 * N];
        __nv_bfloat16 h0 = __float2bfloat16_rn(b0);
        __nv_bfloat16 h1 = __float2bfloat16_rn(b1);
        __nv_bfloat16 h2 = __float2bfloat16_rn(b2);
        __nv_bfloat16 h3 = __float2bfloat16_rn(b3);
        __nv_bfloat16 l0 = __float2bfloat16_rn(b0 - __bfloat162float(h0));
        __nv_bfloat16 l1 = __float2bfloat16_rn(b1 - __bfloat162float(h1));
        __nv_bfloat16 l2 = __float2bfloat16_rn(b2 - __bfloat162float(h2));
        __nv_bfloat16 l3 = __float2bfloat16_rn(b3 - __bfloat162float(h3));
        int chunk_h = g >> 1;
        int sub     = (g & 1) * 8;
        uint32_t off_h = (uint32_t)n * 128 + (uint32_t)((chunk_h ^ (n & 7)) << 4) + sub;
        uint32_t off_l = (uint32_t)n * 128 + (uint32_t)(((chunk_h + 4) ^ (n & 7)) << 4) + sub;
        *(uint2*)(Bs + off_h) = make_uint2(packbf2(h0, h1), packbf2(h2, h3));
        *(uint2*)(Bs + off_l) = make_uint2(packbf2(l0, l1), packbf2(l2, l3));
    }
}

__device__ __forceinline__ void tc_gemm_tile(const float* __restrict__ A,
                                             const float* __restrict__ Bg,
                                             float* __restrict__ C,
                                             int N, int K, int m0, int n0,
                                             char* buf) {
    const int tid  = threadIdx.x;
    const int wid  = tid >> 5;
    const int lane = tid & 31;
    const int wm = wid >> 2;             // 0..1
    const int wn = wid & 3;              // 0..3

    float acc[4][4][4];
#pragma unroll
    for (int i = 0; i < 4; i++)
#pragma unroll
        for (int j = 0; j < 4; j++)
#pragma unroll
            for (int q = 0; q < 4; q++) acc[i][j][q] = 0.f;

    const int S = K / BKG;
    stage_tile(A, Bg, N, K, m0, n0, 0, buf, buf + 16384, tid);
    __syncthreads();

    for (int s = 0; s < S; s++) {
        char* cur = buf + (size_t)(s & 1) * GSTAGE;
        if (s + 1 < S) {
            char* nxt = buf + (size_t)((s + 1) & 1) * GSTAGE;
            stage_tile(A, Bg, N, K, m0, n0, (s + 1) * BKG, nxt, nxt + 16384, tid);
        }
        uint32_t As_b = smem_u32(cur);
        uint32_t Bs_b = smem_u32(cur + 16384);

#pragma unroll
        for (int ks = 0; ks < 2; ks++) {
            uint32_t ah[4][4], al[4][4];
#pragma unroll
            for (int mt = 0; mt < 4; mt++) {
                int row = wm * 64 + mt * 16 + (lane & 15);
                int ch  = ks * 2 + (lane >> 4);
                ldsm_x4(As_b + (uint32_t)row * 128 + (uint32_t)((ch ^ (row & 7)) << 4), ah[mt]);
                ldsm_x4(As_b + (uint32_t)row * 128 + (uint32_t)(((ch + 4) ^ (row & 7)) << 4), al[mt]);
            }
#pragma unroll
            for (int np = 0; np < 2; np++) {
                int g    = lane >> 3;
                int nrow = wn * 32 + np * 16 + ((g >> 1) << 3) + (lane & 7);
                int ch   = ks * 2 + (g & 1);
                uint32_t bh[4], bl[4];
                ldsm_x4(Bs_b + (uint32_t)nrow * 128 + (uint32_t)((ch ^ (nrow & 7)) << 4), bh);
                ldsm_x4(Bs_b + (uint32_t)nrow * 128 + (uint32_t)(((ch + 4) ^ (nrow & 7)) << 4), bl);
#pragma unroll
                for (int j = 0; j < 2; j++) {
                    int nt = np * 2 + j;
#pragma unroll
                    for (int mt = 0; mt < 4; mt++) {
                        mma_bf16(acc[mt][nt], ah[mt], &bh[2 * j]);
                        mma_bf16(acc[mt][nt], ah[mt], &bl[2 * j]);
                        mma_bf16(acc[mt][nt], al[mt], &bh[2 * j]);
                    }
                }
            }
        }
        __syncthreads();
    }

    // Epilogue: acc -> C (float2 stores)
    const int rbase = m0 + wm * 64 + (lane >> 2);
    const int cbase = n0 + wn * 32 + (lane & 3) * 2;
#pragma unroll
    for (int mt = 0; mt < 4; mt++) {
#pragma unroll
        for (int nt = 0; nt < 4; nt++) {
            float* c0 = C + (size_t)(rbase + mt * 16) * N + cbase + nt * 8;
            float* c1 = C + (size_t)(rbase + mt * 16 + 8) * N + cbase + nt * 8;
            *(float2*)c0 = make_float2(acc[mt][nt][0], acc[mt][nt][1]);
            *(float2*)c1 = make_float2(acc[mt][nt][2], acc[mt][nt][3]);
        }
    }
}

// Fused QKV projection: grid.x in [0,24): 0..15 -> Q, 16..19 -> K, 20..23 -> V
__global__ __launch_bounds__(256, 1)
void tc_qkv_kernel(const float* __restrict__ x,
                   const float* __restrict__ wq,
                   const float* __restrict__ wk,
                   const float* __restrict__ wv) {
    extern __shared__ char dynq[];
    const int xb = blockIdx.x;
    const int mb = blockIdx.y;
    const float* Bm;
    float* Cm;
    int N, cb;
    if (xb < 16)      { Bm = wq; Cm = g_q; N = DIM_; cb = xb;      }
    else if (xb < 20) { Bm = wk; Cm = g_k; N = KVD_; cb = xb - 16; }
    else              { Bm = wv; Cm = g_v; N = KVD_; cb = xb - 20; }
    tc_gemm_tile(x, Bm, Cm, N, KDEPTH_, mb * 128, cb * 128, dynq);
}

__global__ __launch_bounds__(256, 1)
void tc_out_kernel(const float* __restrict__ wo, float* __restrict__ out) {
    extern __shared__ char dyno[];
    tc_gemm_tile(g_att, wo, out, DIM_, DIM_, blockIdx.y * 128, blockIdx.x * 128, dyno);
}

// ---------------------------------------------------------------------------
// RoPE (interleaved pairs), in place on g_q / g_k
// ---------------------------------------------------------------------------
__global__ void rope_q_kernel(const float* __restrict__ fc,
                              const float* __restrict__ fs) {
    int idx = blockIdx.x * blockDim.x + threadIdx.x;
    const int total = M_ * H_ * (HD_ / 2);
    if (idx >= total) return;
    int i = idx & 31;
    int h = (idx >> 5) & (H_ - 1);
    int m = idx >> 10;
    int t = m & (T_ - 1);
    float c = fc[t * 32 + i];
    float s = fs[t * 32 + i];
    float2* p = (float2*)&g_q[(size_t)m * DIM_ + h * HD_ + 2 * i];
    float2 v = *p;
    *p = make_float2(v.x * c - v.y * s, v.x * s + v.y * c);
}

__global__ void rope_k_kernel(const float* __restrict__ fc,
                              const float* __restrict__ fs) {
    int idx = blockIdx.x * blockDim.x + threadIdx.x;
    const int total = M_ * HKV_ * (HD_ / 2);
    if (idx >= total) return;
    int i = idx & 31;
    int h = (idx >> 5) & (HKV_ - 1);
    int m = idx >> 8;
    int t = m & (T_ - 1);
    float c = fc[t * 32 + i];
    float s = fs[t * 32 + i];
    float2* p = (float2*)&g_k[(size_t)m * KVD_ + h * HD_ + 2 * i];
    float2 v = *p;
    *p = make_float2(v.x * c - v.y * s, v.x * s + v.y * c);
}

// ---------------------------------------------------------------------------
// Flash-attention (causal, GQA). SIMT version (unchanged, round-1-proven).
// ---------------------------------------------------------------------------
#define QS_LD 65
#define KS_LD 68
#define ATTN_SMEM_BYTES ((64 * QS_LD + 2 * 64 * KS_LD) * 4)

__global__ __launch_bounds__(256)
void attn_kernel() {
    extern __shared__ float sm[];
    float* Qs = sm;
    float* Kt = sm + 64 * QS_LD;
    float* Vs = Kt + 64 * KS_LD;

    const int qt = blockIdx.x;
    const int h  = blockIdx.y;
    const int b  = blockIdx.z;
    const int g  = h >> 2;
    const int tid = threadIdx.x;
    const int r   = tid >> 2;
    const int sub = tid & 3;
    const int qrow0 = qt * 64;

    {
        const float* qrow = g_q + ((size_t)(b * T_ + qrow0 + (tid >> 2))) * DIM_ + h * HD_;
        float* dstrow = &Qs[(tid >> 2) * QS_LD];
#pragma unroll
        for (int it = 0; it < 4; it++) {
            int ch = (tid & 3) + it * 4;
            float4 qv = *(const float4*)(qrow + ch * 4);
            float* d = dstrow + ch * 4;
            d[0] = qv.x; d[1] = qv.y; d[2] = qv.z; d[3] = qv.w;
        }
    }

    float o[16];
#pragma unroll
    for (int i = 0; i < 16; i++) o[i] = 0.f;
    float l = 0.f;
    float mprev = -INFINITY;
    const int iglob = qrow0 + r;

    for (int kt = 0; kt <= qt; kt++) {
        __syncthreads();
        {
            const int jj = tid >> 2;
            const float* krow = g_k + ((size_t)(b * T_ + kt * 64 + jj)) * KVD_ + g * HD_;
            const float* vrow = g_v + ((size_t)(b * T_ + kt * 64 + jj)) * KVD_ + g * HD_;
#pragma unroll
            for (int it = 0; it < 4; it++) {
                int ch = (tid & 3) + it * 4;
                float4 kv = *(const float4*)(krow + ch * 4);
                Kt[(ch * 4 + 0) * KS_LD + jj] = kv.x;
                Kt[(ch * 4 + 1) * KS_LD + jj] = kv.y;
                Kt[(ch * 4 + 2) * KS_LD + jj] = kv.z;
                Kt[(ch * 4 + 3) * KS_LD + jj] = kv.w;
                float4 vv = *(const float4*)(vrow + ch * 4);
                *(float4*)(&Vs[jj * KS_LD + ch * 4]) = vv;
            }
        }
        __syncthreads();

        float s[16];
#pragma unroll
        for (int i = 0; i < 16; i++) s[i] = 0.f;
        const float* qr = &Qs[r * QS_LD];
#pragma unroll 4
        for (int d = 0; d < 64; d++) {
            float qv = qr[d];
            const float* kd = &Kt[d * KS_LD + sub * 16];
#pragma unroll
            for (int i = 0; i < 16; i += 4) {
                float4 kv = *(const float4*)(kd + i);
                s[i]     += qv * kv.x;
                s[i + 1] += qv * kv.y;
                s[i + 2] += qv * kv.z;
                s[i + 3] += qv * kv.w;
            }
        }

        const float scale = 0.125f;
        if (kt == qt) {
#pragma unroll
            for (int i = 0; i < 16; i++) {
                int jglob = kt * 64 + sub * 16 + i;
                s[i] = (jglob <= iglob) ? s[i] * scale : -INFINITY;
            }
        } else {
#pragma unroll
            for (int i = 0; i < 16; i++) s[i] *= scale;
        }

        float mloc = s[0];
#pragma unroll
        for (int i = 1; i < 16; i++) mloc = fmaxf(mloc, s[i]);
        mloc = fmaxf(mloc, __shfl_xor_sync(0xffffffffu, mloc, 1));
        mloc = fmaxf(mloc, __shfl_xor_sync(0xffffffffu, mloc, 2));
        float mnew  = fmaxf(mprev, mloc);
        float alpha = __expf(mprev - mnew);

        __syncthreads();

        float* Ps = Kt;
        float psum = 0.f;
        float* prow = &Ps[r * KS_LD + sub * 16];
#pragma unroll
        for (int i = 0; i < 16; i++) {
            float p = __expf(s[i] - mnew);
            psum += p;
            prow[i] = p;
        }
        psum += __shfl_xor_sync(0xffffffffu, psum, 1);
        psum += __shfl_xor_sync(0xffffffffu, psum, 2);
        l = l * alpha + psum;
        mprev = mnew;
#pragma unroll
        for (int i = 0; i < 16; i++) o[i] *= alpha;
        __syncwarp();

        const float* prow_full = &Ps[r * KS_LD];
#pragma unroll 4
        for (int c = 0; c < 64; c++) {
            float pv = prow_full[c];
            const float* vd = &Vs[c * KS_LD + sub * 16];
#pragma unroll
            for (int i = 0; i < 16; i += 4) {
                float4 vv = *(const float4*)(vd + i);
                o[i]     += pv * vv.x;
                o[i + 1] += pv * vv.y;
                o[i + 2] += pv * vv.z;
                o[i + 3] += pv * vv.w;
            }
        }
    }

    float inv = 1.f / l;
    float* ob = g_att + ((size_t)(b * T_ + iglob)) * DIM_ + h * HD_ + sub * 16;
#pragma unroll
    for (int i = 0; i < 16; i += 4) {
        float4 vv = make_float4(o[i] * inv, o[i + 1] * inv,
                                o[i + 2] * inv, o[i + 3] * inv);
        *(float4*)(ob + i) = vv;
    }
}

// ---------------------------------------------------------------------------
// Launcher
// ---------------------------------------------------------------------------
extern "C" void kernel_launch(void* const* d_in, const int* in_sizes, int n_in,
                              void* d_out, int out_size) {
    const float* x  = (const float*)d_in[0];
    const float* fc = (const float*)d_in[1];
    const float* fs = (const float*)d_in[2];
    const float* wq = (const float*)d_in[3];
    const float* wk = (const float*)d_in[4];
    const float* wv = (const float*)d_in[5];
    const float* wo = (const float*)d_in[6];
    float* out = (float*)d_out;

    cudaFuncSetAttribute(tc_qkv_kernel,
                         cudaFuncAttributeMaxDynamicSharedMemorySize,
                         GEMM_SMEM_BYTES);
    cudaFuncSetAttribute(tc_out_kernel,
                         cudaFuncAttributeMaxDynamicSharedMemorySize,
                         GEMM_SMEM_BYTES);
    cudaFuncSetAttribute(attn_kernel,
                         cudaFuncAttributeMaxDynamicSharedMemorySize,
                         ATTN_SMEM_BYTES);

    // 1) Fused QKV projections (HMMA bf16 3x-split)
    tc_qkv_kernel<<<dim3(24, 32), 256, GEMM_SMEM_BYTES>>>(x, wq, wk, wv);

    // 2) RoPE on Q and K (in place)
    rope_q_kernel<<<(M_ * H_ * 32 + 255) / 256, 256>>>(fc, fs);
    rope_k_kernel<<<(M_ * HKV_ * 32 + 255) / 256, 256>>>(fc, fs);

    // 3) Causal GQA flash attention (SIMT)
    attn_kernel<<<dim3(T_ / 64, H_, B_), 256, ATTN_SMEM_BYTES>>>();

    // 4) Output projection (HMMA bf16 3x-split)
    tc_out_kernel<<<dim3(16, 32), 256, GEMM_SMEM_BYTES>>>(wo, out);
}

// round 4
// speedup vs baseline: 4.1750x; 3.3988x over previous
#include <cuda_runtime.h>
#include <cuda_bf16.h>
#include <math.h>
#include <stdint.h>

// Problem constants
#define B_   2
#define T_   2048
#define DIM_ 2048
#define H_   32
#define HKV_ 8
#define HD_  64
#define NREP_ 4
#define M_   (B_ * T_)            // 4096
#define KVD_ (HKV_ * HD_)         // 512
#define KDEPTH_ 2048

// ---------------------------------------------------------------------------
// Scratch (device globals; no allocation allowed)
// ---------------------------------------------------------------------------
__device__ __nv_bfloat16 g_qh[(size_t)M_ * DIM_];   // rope'd, pre-scaled Q hi
__device__ __nv_bfloat16 g_ql[(size_t)M_ * DIM_];   // lo
__device__ __nv_bfloat16 g_kh[(size_t)M_ * KVD_];   // rope'd K hi
__device__ __nv_bfloat16 g_kl[(size_t)M_ * KVD_];
__device__ __nv_bfloat16 g_vth[(size_t)KVD_ * M_];  // V transposed [col][row]
__device__ __nv_bfloat16 g_vtl[(size_t)KVD_ * M_];
__device__ float g_att[(size_t)M_ * DIM_];          // attention out (fp32)

// ---------------------------------------------------------------------------
// Helpers
// ---------------------------------------------------------------------------
__device__ __forceinline__ uint32_t smem_u32(const void* p) {
    uint32_t a;
    asm("{ .reg .u64 t; cvta.to.shared.u64 t, %1; cvt.u32.u64 %0, t; }"
        : "=r"(a) : "l"(p));
    return a;
}

__device__ __forceinline__ uint32_t packbf2(__nv_bfloat16 a, __nv_bfloat16 b) {
    return ((uint32_t)__bfloat16_as_ushort(b) << 16) | (uint32_t)__bfloat16_as_ushort(a);
}

__device__ __forceinline__ void ldsm_x4(uint32_t addr, uint32_t* r) {
    asm volatile("ldmatrix.sync.aligned.m8n8.x4.shared.b16 {%0,%1,%2,%3}, [%4];"
                 : "=r"(r[0]), "=r"(r[1]), "=r"(r[2]), "=r"(r[3]) : "r"(addr));
}

__device__ __forceinline__ void mma_bf16(float* c, const uint32_t* a, const uint32_t* b) {
    asm volatile(
        "mma.sync.aligned.m16n8k16.row.col.f32.bf16.bf16.f32 "
        "{%0,%1,%2,%3}, {%4,%5,%6,%7}, {%8,%9}, {%0,%1,%2,%3};"
        : "+f"(c[0]), "+f"(c[1]), "+f"(c[2]), "+f"(c[3])
        : "r"(a[0]), "r"(a[1]), "r"(a[2]), "r"(a[3]), "r"(b[0]), "r"(b[1]));
}

__device__ __forceinline__ void split1(float v, __nv_bfloat16& h, __nv_bfloat16& l) {
    h = __float2bfloat16_rn(v);
    l = __float2bfloat16_rn(v - __bfloat162float(h));
}

// ---------------------------------------------------------------------------
// HMMA bf16 (3-term split) GEMM: 128x128 tile, BK=32, double-buffered.
// Epilogue modes: 0 = fp32 store, 1 = rope+scale+split bf16, 2 = split+transpose
// ---------------------------------------------------------------------------
#define BKG 32
#define GSTAGE 32768
#define GEMM_SMEM_BYTES (2 * GSTAGE)

__device__ __forceinline__ void stage_tile(const float* __restrict__ A,
                                           const float* __restrict__ Bg,
                                           int N, int K, int m0, int n0, int k0,
                                           char* As, char* Bs, int tid) {
#pragma unroll
    for (int it = 0; it < 4; it++) {
        int idx = it * 256 + tid;
        int r  = idx >> 3;
        int c4 = idx & 7;
        float4 v = *(const float4*)(A + (size_t)(m0 + r) * K + k0 + c4 * 4);
        __nv_bfloat16 hx, hy, hz, hw, lx, ly, lz, lw;
        split1(v.x, hx, lx); split1(v.y, hy, ly);
        split1(v.z, hz, lz); split1(v.w, hw, lw);
        int chunk_h = c4 >> 1;
        int sub     = (c4 & 1) * 8;
        uint32_t off_h = (uint32_t)r * 128 + (uint32_t)((chunk_h ^ (r & 7)) << 4) + sub;
        uint32_t off_l = (uint32_t)r * 128 + (uint32_t)(((chunk_h + 4) ^ (r & 7)) << 4) + sub;
        *(uint2*)(As + off_h) = make_uint2(packbf2(hx, hy), packbf2(hz, hw));
        *(uint2*)(As + off_l) = make_uint2(packbf2(lx, ly), packbf2(lz, lw));
    }
#pragma unroll
    for (int it = 0; it < 4; it++) {
        int idx = it * 256 + tid;
        int n = idx & 127;
        int g = idx >> 7;
        const float* bp = Bg + (size_t)(k0 + g * 4) * N + n0 + n;
        float b0 = bp[0];
        float b1 = bp[(size_t)N];
        float b2 = bp[(size_t)2 * N];
        float b3 = bp[(size_t)3 * N];
        __nv_bfloat16 h0, h1, h2, h3, l0, l1, l2, l3;
        split1(b0, h0, l0); split1(b1, h1, l1);
        split1(b2, h2, l2); split1(b3, h3, l3);
        int chunk_h = g >> 1;
        int sub     = (g & 1) * 8;
        uint32_t off_h = (uint32_t)n * 128 + (uint32_t)((chunk_h ^ (n & 7)) << 4) + sub;
        uint32_t off_l = (uint32_t)n * 128 + (uint32_t)(((chunk_h + 4) ^ (n & 7)) << 4) + sub;
        *(uint2*)(Bs + off_h) = make_uint2(packbf2(h0, h1), packbf2(h2, h3));
        *(uint2*)(Bs + off_l) = make_uint2(packbf2(l0, l1), packbf2(l2, l3));
    }
}

__device__ __forceinline__ void tc_gemm_tile(const float* __restrict__ A,
                                             const float* __restrict__ Bg,
                                             int N, int K, int m0, int n0,
                                             char* buf, int mode,
                                             float* __restrict__ C,
                                             __nv_bfloat16* __restrict__ outh,
                                             __nv_bfloat16* __restrict__ outl,
                                             const float* __restrict__ fc,
                                             const float* __restrict__ fs,
                                             float oscale) {
    const int tid  = threadIdx.x;
    const int wid  = tid >> 5;
    const int lane = tid & 31;
    const int wm = wid >> 2;
    const int wn = wid & 3;

    float acc[4][4][4];
#pragma unroll
    for (int i = 0; i < 4; i++)
#pragma unroll
        for (int j = 0; j < 4; j++)
#pragma unroll
            for (int q = 0; q < 4; q++) acc[i][j][q] = 0.f;

    const int S = K / BKG;
    stage_tile(A, Bg, N, K, m0, n0, 0, buf, buf + 16384, tid);
    __syncthreads();

    for (int s = 0; s < S; s++) {
        char* cur = buf + (size_t)(s & 1) * GSTAGE;
        if (s + 1 < S) {
            char* nxt = buf + (size_t)((s + 1) & 1) * GSTAGE;
            stage_tile(A, Bg, N, K, m0, n0, (s + 1) * BKG, nxt, nxt + 16384, tid);
        }
        uint32_t As_b = smem_u32(cur);
        uint32_t Bs_b = smem_u32(cur + 16384);

#pragma unroll
        for (int ks = 0; ks < 2; ks++) {
            uint32_t ah[4][4], al[4][4];
#pragma unroll
            for (int mt = 0; mt < 4; mt++) {
                int row = wm * 64 + mt * 16 + (lane & 15);
                int ch  = ks * 2 + (lane >> 4);
                ldsm_x4(As_b + (uint32_t)row * 128 + (uint32_t)((ch ^ (row & 7)) << 4), ah[mt]);
                ldsm_x4(As_b + (uint32_t)row * 128 + (uint32_t)(((ch + 4) ^ (row & 7)) << 4), al[mt]);
            }
#pragma unroll
            for (int np = 0; np < 2; np++) {
                int g    = lane >> 3;
                int nrow = wn * 32 + np * 16 + ((g >> 1) << 3) + (lane & 7);
                int ch   = ks * 2 + (g & 1);
                uint32_t bh[4], bl[4];
                ldsm_x4(Bs_b + (uint32_t)nrow * 128 + (uint32_t)((ch ^ (nrow & 7)) << 4), bh);
                ldsm_x4(Bs_b + (uint32_t)nrow * 128 + (uint32_t)(((ch + 4) ^ (nrow & 7)) << 4), bl);
#pragma unroll
                for (int j = 0; j < 2; j++) {
                    int nt = np * 2 + j;
#pragma unroll
                    for (int mt = 0; mt < 4; mt++) {
                        mma_bf16(acc[mt][nt], ah[mt], &bh[2 * j]);
                        mma_bf16(acc[mt][nt], ah[mt], &bl[2 * j]);
                        mma_bf16(acc[mt][nt], al[mt], &bh[2 * j]);
                    }
                }
            }
        }
        __syncthreads();
    }

    const int rbase = m0 + wm * 64 + (lane >> 2);
    const int cbase = n0 + wn * 32 + (lane & 3) * 2;
#pragma unroll
    for (int mt = 0; mt < 4; mt++) {
#pragma unroll
        for (int nt = 0; nt < 4; nt++) {
            int r0 = rbase + mt * 16;
            int r1 = r0 + 8;
            int c  = cbase + nt * 8;
            float a0 = acc[mt][nt][0], a1 = acc[mt][nt][1];
            float a2 = acc[mt][nt][2], a3 = acc[mt][nt][3];
            if (mode == 0) {
                *(float2*)(C + (size_t)r0 * N + c) = make_float2(a0, a1);
                *(float2*)(C + (size_t)r1 * N + c) = make_float2(a2, a3);
            } else if (mode == 1) {
                int i  = (c & 63) >> 1;
                int t0 = r0 & (T_ - 1);
                int t1 = r1 & (T_ - 1);
                float cs0 = fc[t0 * 32 + i], sn0 = fs[t0 * 32 + i];
                float cs1 = fc[t1 * 32 + i], sn1 = fs[t1 * 32 + i];
                float u0 = (a0 * cs0 - a1 * sn0) * oscale;
                float u1 = (a0 * sn0 + a1 * cs0) * oscale;
                float v0 = (a2 * cs1 - a3 * sn1) * oscale;
                float v1 = (a2 * sn1 + a3 * cs1) * oscale;
                __nv_bfloat16 h0, h1, h2, h3, l0, l1, l2, l3;
                split1(u0, h0, l0); split1(u1, h1, l1);
                split1(v0, h2, l2); split1(v1, h3, l3);
                __nv_bfloat162 th0; th0.x = h0; th0.y = h1;
                __nv_bfloat162 tl0; tl0.x = l0; tl0.y = l1;
                __nv_bfloat162 th1; th1.x = h2; th1.y = h3;
                __nv_bfloat162 tl1; tl1.x = l2; tl1.y = l3;
                *(__nv_bfloat162*)(outh + (size_t)r0 * N + c) = th0;
                *(__nv_bfloat162*)(outl + (size_t)r0 * N + c) = tl0;
                *(__nv_bfloat162*)(outh + (size_t)r1 * N + c) = th1;
                *(__nv_bfloat162*)(outl + (size_t)r1 * N + c) = tl1;
            } else {
                // transpose split: out[col][row]
                __nv_bfloat16 h, l;
                split1(a0, h, l);
                outh[(size_t)c * M_ + r0] = h;       outl[(size_t)c * M_ + r0] = l;
                split1(a1, h, l);
                outh[(size_t)(c + 1) * M_ + r0] = h; outl[(size_t)(c + 1) * M_ + r0] = l;
                split1(a2, h, l);
                outh[(size_t)c * M_ + r1] = h;       outl[(size_t)c * M_ + r1] = l;
                split1(a3, h, l);
                outh[(size_t)(c + 1) * M_ + r1] = h; outl[(size_t)(c + 1) * M_ + r1] = l;
            }
        }
    }
}

// Fused QKV projection + RoPE + bf16 hi/lo split (+ V transpose)
__global__ __launch_bounds__(256, 1)
void tc_qkv_kernel(const float* __restrict__ x,
                   const float* __restrict__ wq,
                   const float* __restrict__ wk,
                   const float* __restrict__ wv,
                   const float* __restrict__ fc,
                   const float* __restrict__ fs) {
    extern __shared__ char dynq[];
    const int xb = blockIdx.x;
    const int mb = blockIdx.y;
    if (xb < 16) {
        tc_gemm_tile(x, wq, DIM_, KDEPTH_, mb * 128, xb * 128, dynq,
                     1, nullptr, g_qh, g_ql, fc, fs, 0.125f);
    } else if (xb < 20) {
        tc_gemm_tile(x, wk, KVD_, KDEPTH_, mb * 128, (xb - 16) * 128, dynq,
                     1, nullptr, g_kh, g_kl, fc, fs, 1.0f);
    } else {
        tc_gemm_tile(x, wv, KVD_, KDEPTH_, mb * 128, (xb - 20) * 128, dynq,
                     2, nullptr, g_vth, g_vtl, nullptr, nullptr, 1.0f);
    }
}

__global__ __launch_bounds__(256, 1)
void tc_out_kernel(const float* __restrict__ wo, float* __restrict__ out) {
    extern __shared__ char dyno[];
    tc_gemm_tile(g_att, wo, DIM_, DIM_, blockIdx.y * 128, blockIdx.x * 128, dyno,
                 0, out, nullptr, nullptr, nullptr, nullptr, 1.0f);
}

// ---------------------------------------------------------------------------
// Tensor-core flash attention (causal, GQA), bf16 3-term split.
// CTA = 64 q rows of one (b,h); 4 warps, each warp 16 rows x full 64-key width.
// smem: Qh/Ql (8KB each) + Kh/Kl (8KB each) + VTh/VTl (8KB each) = 48KB.
// ---------------------------------------------------------------------------
#define ATTN_SMEM_BYTES (48 * 1024)

__global__ __launch_bounds__(128)
void attn_mma_kernel() {
    extern __shared__ char sm[];
    char* sQh = sm;
    char* sQl = sm + 8192;
    char* sKh = sm + 16384;
    char* sKl = sm + 24576;
    char* sVh = sm + 32768;
    char* sVl = sm + 40960;

    const int qt = blockIdx.x;        // q tile (64 rows)
    const int h  = blockIdx.y;
    const int b  = blockIdx.z;
    const int g  = h >> 2;
    const int tid  = threadIdx.x;
    const int w    = tid >> 5;
    const int lane = tid & 31;
    const int q0 = qt * 64;

    // ---- stage Q tile (hi/lo) ----
    {
        const __nv_bfloat16* qh_g = g_qh + (size_t)(b * T_ + q0) * DIM_ + h * HD_;
        const __nv_bfloat16* ql_g = g_ql + (size_t)(b * T_ + q0) * DIM_ + h * HD_;
#pragma unroll
        for (int it = 0; it < 4; it++) {
            int idx = it * 128 + tid;
            int row = idx >> 3;
            int c4  = idx & 7;
            uint32_t soff = (uint32_t)row * 128 + (uint32_t)((c4 ^ (row & 7)) << 4);
            *(uint4*)(sQh + soff) = *(const uint4*)(qh_g + (size_t)row * DIM_ + c4 * 8);
            *(uint4*)(sQl + soff) = *(const uint4*)(ql_g + (size_t)row * DIM_ + c4 * 8);
        }
    }
    __syncthreads();

    // ---- load Q fragments (persistent in registers) ----
    uint32_t qh[4][4], ql[4][4];
    {
        uint32_t Qh_b = smem_u32(sQh);
        uint32_t Ql_b = smem_u32(sQl);
        int row = w * 16 + (lane & 15);
        int chb = lane >> 4;
#pragma unroll
        for (int kf = 0; kf < 4; kf++) {
            int ch = kf * 2 + chb;
            uint32_t off = (uint32_t)row * 128 + (uint32_t)((ch ^ (row & 7)) << 4);
            ldsm_x4(Qh_b + off, qh[kf]);
            ldsm_x4(Ql_b + off, ql[kf]);
        }
    }

    float o[8][4];
#pragma unroll
    for (int dt = 0; dt < 8; dt++)
#pragma unroll
        for (int q = 0; q < 4; q++) o[dt][q] = 0.f;
    float m0 = -INFINITY, m1 = -INFINITY, l0 = 0.f, l1 = 0.f;

    const uint32_t Kh_b = smem_u32(sKh);
    const uint32_t Kl_b = smem_u32(sKl);
    const uint32_t Vh_b = smem_u32(sVh);
    const uint32_t Vl_b = smem_u32(sVl);

    const int rg0 = q0 + w * 16 + (lane >> 2);   // global q row of c0,c1
    const int rg1 = rg0 + 8;

    for (int kt = 0; kt <= qt; kt++) {
        __syncthreads();
        // ---- stage K, V^T tiles (hi/lo) ----
        {
            const __nv_bfloat16* kh_g = g_kh + (size_t)(b * T_ + kt * 64) * KVD_ + g * HD_;
            const __nv_bfloat16* kl_g = g_kl + (size_t)(b * T_ + kt * 64) * KVD_ + g * HD_;
            const __nv_bfloat16* vh_g = g_vth + (size_t)(g * HD_) * M_ + b * T_ + kt * 64;
            const __nv_bfloat16* vl_g = g_vtl + (size_t)(g * HD_) * M_ + b * T_ + kt * 64;
#pragma unroll
            for (int it = 0; it < 4; it++) {
                int idx = it * 128 + tid;
                int row = idx >> 3;
                int c4  = idx & 7;
                uint32_t soff = (uint32_t)row * 128 + (uint32_t)((c4 ^ (row & 7)) << 4);
                *(uint4*)(sKh + soff) = *(const uint4*)(kh_g + (size_t)row * KVD_ + c4 * 8);
                *(uint4*)(sKl + soff) = *(const uint4*)(kl_g + (size_t)row * KVD_ + c4 * 8);
                *(uint4*)(sVh + soff) = *(const uint4*)(vh_g + (size_t)row * M_ + c4 * 8);
                *(uint4*)(sVl + soff) = *(const uint4*)(vl_g + (size_t)row * M_ + c4 * 8);
            }
        }
        __syncthreads();

        // ---- S = Q K^T (3-term split) ----
        float s[8][4];
#pragma unroll
        for (int nt = 0; nt < 8; nt++)
#pragma unroll
            for (int q = 0; q < 4; q++) s[nt][q] = 0.f;

#pragma unroll
        for (int kf = 0; kf < 4; kf++) {
#pragma unroll
            for (int np = 0; np < 4; np++) {
                int gg   = lane >> 3;
                int nrow = np * 16 + ((gg >> 1) << 3) + (lane & 7);
                int ch   = kf * 2 + (gg & 1);
                uint32_t off = (uint32_t)nrow * 128 + (uint32_t)((ch ^ (nrow & 7)) << 4);
                uint32_t bh[4], bl[4];
                ldsm_x4(Kh_b + off, bh);
                ldsm_x4(Kl_b + off, bl);
#pragma unroll
                for (int j = 0; j < 2; j++) {
                    int nt = np * 2 + j;
                    mma_bf16(s[nt], qh[kf], &bh[2 * j]);
                    mma_bf16(s[nt], qh[kf], &bl[2 * j]);
                    mma_bf16(s[nt], ql[kf], &bh[2 * j]);
                }
            }
        }

        // ---- causal mask (diagonal tile only) ----
        if (kt == qt) {
            int cb = kt * 64 + (lane & 3) * 2;
#pragma unroll
            for (int nt = 0; nt < 8; nt++) {
                int c = cb + nt * 8;
                if (c > rg0)     s[nt][0] = -INFINITY;
                if (c + 1 > rg0) s[nt][1] = -INFINITY;
                if (c > rg1)     s[nt][2] = -INFINITY;
                if (c + 1 > rg1) s[nt][3] = -INFINITY;
            }
        }

        // ---- online softmax ----
        float mx0 = s[0][0], mx1 = s[0][2];
#pragma unroll
        for (int nt = 0; nt < 8; nt++) {
            mx0 = fmaxf(mx0, fmaxf(s[nt][0], s[nt][1]));
            mx1 = fmaxf(mx1, fmaxf(s[nt][2], s[nt][3]));
        }
        mx0 = fmaxf(mx0, __shfl_xor_sync(0xffffffffu, mx0, 1));
        mx0 = fmaxf(mx0, __shfl_xor_sync(0xffffffffu, mx0, 2));
        mx1 = fmaxf(mx1, __shfl_xor_sync(0xffffffffu, mx1, 1));
        mx1 = fmaxf(mx1, __shfl_xor_sync(0xffffffffu, mx1, 2));

        float mn0 = fmaxf(fmaxf(m0, mx0), -1e30f);
        float mn1 = fmaxf(fmaxf(m1, mx1), -1e30f);
        float a0 = __expf(m0 - mn0);
        float a1 = __expf(m1 - mn1);
        m0 = mn0; m1 = mn1;

        float sum0 = 0.f, sum1 = 0.f;
#pragma unroll
        for (int nt = 0; nt < 8; nt++) {
            s[nt][0] = __expf(s[nt][0] - mn0);
            s[nt][1] = __expf(s[nt][1] - mn0);
            s[nt][2] = __expf(s[nt][2] - mn1);
            s[nt][3] = __expf(s[nt][3] - mn1);
            sum0 += s[nt][0] + s[nt][1];
            sum1 += s[nt][2] + s[nt][3];
        }
        sum0 += __shfl_xor_sync(0xffffffffu, sum0, 1);
        sum0 += __shfl_xor_sync(0xffffffffu, sum0, 2);
        sum1 += __shfl_xor_sync(0xffffffffu, sum1, 1);
        sum1 += __shfl_xor_sync(0xffffffffu, sum1, 2);
        l0 = l0 * a0 + sum0;
        l1 = l1 * a1 + sum1;

#pragma unroll
        for (int dt = 0; dt < 8; dt++) {
            o[dt][0] *= a0; o[dt][1] *= a0;
            o[dt][2] *= a1; o[dt][3] *= a1;
        }

        // ---- O += P V (3-term split; P frags built from S regs) ----
#pragma unroll
        for (int kf = 0; kf < 4; kf++) {
            uint32_t aph[4], apl[4];
#pragma unroll
            for (int half = 0; half < 2; half++) {
                float p0 = s[2 * kf + half][0], p1 = s[2 * kf + half][1];
                float p2 = s[2 * kf + half][2], p3 = s[2 * kf + half][3];
                __nv_bfloat16 h0, h1, h2, h3, e0, e1, e2, e3;
                split1(p0, h0, e0); split1(p1, h1, e1);
                split1(p2, h2, e2); split1(p3, h3, e3);
                aph[2 * half]     = packbf2(h0, h1);
                aph[2 * half + 1] = packbf2(h2, h3);
                apl[2 * half]     = packbf2(e0, e1);
                apl[2 * half + 1] = packbf2(e2, e3);
            }
#pragma unroll
            for (int dp = 0; dp < 4; dp++) {
                int gg   = lane >> 3;
                int drow = dp * 16 + ((gg >> 1) << 3) + (lane & 7);
                int ch   = kf * 2 + (gg & 1);
                uint32_t off = (uint32_t)drow * 128 + (uint32_t)((ch ^ (drow & 7)) << 4);
                uint32_t vh[4], vl[4];
                ldsm_x4(Vh_b + off, vh);
                ldsm_x4(Vl_b + off, vl);
#pragma unroll
                for (int j = 0; j < 2; j++) {
                    int dt = dp * 2 + j;
                    mma_bf16(o[dt], aph, &vh[2 * j]);
                    mma_bf16(o[dt], aph, &vl[2 * j]);
                    mma_bf16(o[dt], apl, &vh[2 * j]);
                }
            }
        }
    }

    // ---- epilogue ----
    float inv0 = 1.f / l0;
    float inv1 = 1.f / l1;
    float* out0 = g_att + (size_t)(b * T_ + rg0) * DIM_ + h * HD_ + (lane & 3) * 2;
    float* out1 = g_att + (size_t)(b * T_ + rg1) * DIM_ + h * HD_ + (lane & 3) * 2;
#pragma unroll
    for (int dt = 0; dt < 8; dt++) {
        *(float2*)(out0 + dt * 8) = make_float2(o[dt][0] * inv0, o[dt][1] * inv0);
        *(float2*)(out1 + dt * 8) = make_float2(o[dt][2] * inv1, o[dt][3] * inv1);
    }
}

// ---------------------------------------------------------------------------
// Launcher
// ---------------------------------------------------------------------------
extern "C" void kernel_launch(void* const* d_in, const int* in_sizes, int n_in,
                              void* d_out, int out_size) {
    const float* x  = (const float*)d_in[0];
    const float* fc = (const float*)d_in[1];
    const float* fs = (const float*)d_in[2];
    const float* wq = (const float*)d_in[3];
    const float* wk = (const float*)d_in[4];
    const float* wv = (const float*)d_in[5];
    const float* wo = (const float*)d_in[6];
    float* out = (float*)d_out;

    cudaFuncSetAttribute(tc_qkv_kernel,
                         cudaFuncAttributeMaxDynamicSharedMemorySize, GEMM_SMEM_BYTES);
    cudaFuncSetAttribute(tc_out_kernel,
                         cudaFuncAttributeMaxDynamicSharedMemorySize, GEMM_SMEM_BYTES);
    cudaFuncSetAttribute(attn_mma_kernel,
                         cudaFuncAttributeMaxDynamicSharedMemorySize, ATTN_SMEM_BYTES);

    // 1) QKV projections + fused RoPE + bf16 hi/lo split (+ V transpose)
    tc_qkv_kernel<<<dim3(24, 32), 256, GEMM_SMEM_BYTES>>>(x, wq, wk, wv, fc, fs);

    // 2) Tensor-core causal GQA flash attention
    attn_mma_kernel<<<dim3(T_ / 64, H_, B_), 128, ATTN_SMEM_BYTES>>>();

    // 3) Output projection
    tc_out_kernel<<<dim3(16, 32), 256, GEMM_SMEM_BYTES>>>(wo, out);
}

// round 8
// speedup vs baseline: 4.7241x; 1.1315x over previous
#include <cuda_runtime.h>
#include <cuda_bf16.h>
#include <math.h>
#include <stdint.h>

// Problem constants
#define B_   2
#define T_   2048
#define DIM_ 2048
#define H_   32
#define HKV_ 8
#define HD_  64
#define M_   (B_ * T_)            // 4096
#define KVD_ (HKV_ * HD_)         // 512
#define KDEPTH_ 2048

// ---------------------------------------------------------------------------
// Scratch (device globals; no allocation allowed)
// ---------------------------------------------------------------------------
__device__ __nv_bfloat16 g_xh[(size_t)M_ * DIM_];
__device__ __nv_bfloat16 g_xl[(size_t)M_ * DIM_];
__device__ __nv_bfloat16 g_wqt_h[(size_t)DIM_ * DIM_];   // [n][k]
__device__ __nv_bfloat16 g_wqt_l[(size_t)DIM_ * DIM_];
__device__ __nv_bfloat16 g_wkt_h[(size_t)KVD_ * DIM_];
__device__ __nv_bfloat16 g_wkt_l[(size_t)KVD_ * DIM_];
__device__ __nv_bfloat16 g_wvt_h[(size_t)KVD_ * DIM_];
__device__ __nv_bfloat16 g_wvt_l[(size_t)KVD_ * DIM_];
__device__ __nv_bfloat16 g_wot_h[(size_t)DIM_ * DIM_];
__device__ __nv_bfloat16 g_wot_l[(size_t)DIM_ * DIM_];

__device__ __nv_bfloat16 g_qh[(size_t)M_ * DIM_];   // rope'd, pre-scaled Q
__device__ __nv_bfloat16 g_ql[(size_t)M_ * DIM_];
__device__ __nv_bfloat16 g_kh[(size_t)M_ * KVD_];
__device__ __nv_bfloat16 g_kl[(size_t)M_ * KVD_];
__device__ __nv_bfloat16 g_vth[(size_t)KVD_ * M_];  // V transposed [d][t]
__device__ __nv_bfloat16 g_vtl[(size_t)KVD_ * M_];
__device__ __nv_bfloat16 g_atth[(size_t)M_ * DIM_]; // attention out hi/lo
__device__ __nv_bfloat16 g_attl[(size_t)M_ * DIM_];

// ---------------------------------------------------------------------------
// Helpers
// ---------------------------------------------------------------------------
__device__ __forceinline__ uint32_t smem_u32(const void* p) {
    uint32_t a;
    asm("{ .reg .u64 t; cvta.to.shared.u64 t, %1; cvt.u32.u64 %0, t; }"
        : "=r"(a) : "l"(p));
    return a;
}
__device__ __forceinline__ uint32_t packbf2(__nv_bfloat16 a, __nv_bfloat16 b) {
    return ((uint32_t)__bfloat16_as_ushort(b) << 16) | (uint32_t)__bfloat16_as_ushort(a);
}
__device__ __forceinline__ void ldsm_x4(uint32_t addr, uint32_t* r) {
    asm volatile("ldmatrix.sync.aligned.m8n8.x4.shared.b16 {%0,%1,%2,%3}, [%4];"
                 : "=r"(r[0]), "=r"(r[1]), "=r"(r[2]), "=r"(r[3]) : "r"(addr));
}
__device__ __forceinline__ void mma_bf16(float* c, const uint32_t* a, const uint32_t* b) {
    asm volatile(
        "mma.sync.aligned.m16n8k16.row.col.f32.bf16.bf16.f32 "
        "{%0,%1,%2,%3}, {%4,%5,%6,%7}, {%8,%9}, {%0,%1,%2,%3};"
        : "+f"(c[0]), "+f"(c[1]), "+f"(c[2]), "+f"(c[3])
        : "r"(a[0]), "r"(a[1]), "r"(a[2]), "r"(a[3]), "r"(b[0]), "r"(b[1]));
}
__device__ __forceinline__ void split1(float v, __nv_bfloat16& h, __nv_bfloat16& l) {
    h = __float2bfloat16_rn(v);
    l = __float2bfloat16_rn(v - __bfloat162float(h));
}

// ---------------------------------------------------------------------------
// Prepass: split x, transpose+split weights.
// NOTE: destination __device__ globals are resolved INSIDE device code — a
// __device__ symbol passed as a host-side kernel arg is the HOST shadow
// address (silently writable on GB300 via ATS) -> that was the r5-r7 bug.
// ---------------------------------------------------------------------------
__global__ void split_x_kernel(const float* __restrict__ x) {
    size_t idx = (size_t)blockIdx.x * 256 + threadIdx.x;
    float4 v = ((const float4*)x)[idx];
    __nv_bfloat16 hx, hy, hz, hw, lx, ly, lz, lw;
    split1(v.x, hx, lx); split1(v.y, hy, ly);
    split1(v.z, hz, lz); split1(v.w, hw, lw);
    *(uint2*)(g_xh + idx * 4) = make_uint2(packbf2(hx, hy), packbf2(hz, hw));
    *(uint2*)(g_xl + idx * 4) = make_uint2(packbf2(lx, ly), packbf2(lz, lw));
}

__global__ void tsplit_kernel(const float* __restrict__ src, int which,
                              int K, int N) {   // src [K,N] -> dst [N,K]
    __nv_bfloat16* dsth;
    __nv_bfloat16* dstl;
    if (which == 0)      { dsth = g_wqt_h; dstl = g_wqt_l; }
    else if (which == 1) { dsth = g_wkt_h; dstl = g_wkt_l; }
    else if (which == 2) { dsth = g_wvt_h; dstl = g_wvt_l; }
    else                 { dsth = g_wot_h; dstl = g_wot_l; }

    __shared__ float tile[32][33];
    int n0 = blockIdx.x * 32, k0 = blockIdx.y * 32;
    int tx = threadIdx.x, ty = threadIdx.y;
#pragma unroll
    for (int i = 0; i < 4; i++)
        tile[ty + i * 8][tx] = src[(size_t)(k0 + ty + i * 8) * N + n0 + tx];
    __syncthreads();
#pragma unroll
    for (int i = 0; i < 4; i++) {
        float v = tile[tx][ty + i * 8];
        __nv_bfloat16 h, l;
        split1(v, h, l);
        dsth[(size_t)(n0 + ty + i * 8) * K + k0 + tx] = h;
        dstl[(size_t)(n0 + ty + i * 8) * K + k0 + tx] = l;
    }
}

// ---------------------------------------------------------------------------
// HMMA bf16 (3-term split) GEMM: 128x128 tile, BK=32, double-buffered
// SYNCHRONOUS staging of PRE-SPLIT bf16 inputs (zero conversion in hot loop).
// A[M,K] hi/lo (k-contig), B[N,K] hi/lo (k-contig).
// smem per stage 32KB; 2 stages = 64KB dynamic smem.
// ---------------------------------------------------------------------------
#define BKG 32
#define GSTAGE 32768
#define GEMM_SMEM_BYTES (2 * GSTAGE)

__device__ __forceinline__ void stage_presplit(const __nv_bfloat16* __restrict__ Ah,
                                               const __nv_bfloat16* __restrict__ Al,
                                               const __nv_bfloat16* __restrict__ Bh,
                                               const __nv_bfloat16* __restrict__ Bl,
                                               int K, int m0, int n0, int k0,
                                               char* As, char* Bs, int tid) {
#pragma unroll
    for (int it = 0; it < 4; it++) {
        int idx = it * 256 + tid;
        int r = idx >> 3, c = idx & 7;
        const __nv_bfloat16* src = (c < 4)
            ? (Ah + (size_t)(m0 + r) * K + k0 + c * 8)
            : (Al + (size_t)(m0 + r) * K + k0 + (c - 4) * 8);
        *(uint4*)(As + (uint32_t)r * 128 + (uint32_t)((c ^ (r & 7)) << 4)) =
            *(const uint4*)src;
    }
#pragma unroll
    for (int it = 0; it < 4; it++) {
        int idx = it * 256 + tid;
        int r = idx >> 3, c = idx & 7;
        const __nv_bfloat16* src = (c < 4)
            ? (Bh + (size_t)(n0 + r) * K + k0 + c * 8)
            : (Bl + (size_t)(n0 + r) * K + k0 + (c - 4) * 8);
        *(uint4*)(Bs + (uint32_t)r * 128 + (uint32_t)((c ^ (r & 7)) << 4)) =
            *(const uint4*)src;
    }
}

__device__ __forceinline__ void tc_gemm_tile(const __nv_bfloat16* __restrict__ Ah,
                                             const __nv_bfloat16* __restrict__ Al,
                                             const __nv_bfloat16* __restrict__ Bh,
                                             const __nv_bfloat16* __restrict__ Bl,
                                             int N, int K, int m0, int n0,
                                             char* buf, int mode,
                                             float* __restrict__ C,
                                             __nv_bfloat16* __restrict__ outh,
                                             __nv_bfloat16* __restrict__ outl,
                                             const float* __restrict__ fc,
                                             const float* __restrict__ fs,
                                             float oscale) {
    const int tid  = threadIdx.x;
    const int wid  = tid >> 5;
    const int lane = tid & 31;
    const int wm = wid >> 2;
    const int wn = wid & 3;

    float acc[4][4][4];
#pragma unroll
    for (int i = 0; i < 4; i++)
#pragma unroll
        for (int j = 0; j < 4; j++)
#pragma unroll
            for (int q = 0; q < 4; q++) acc[i][j][q] = 0.f;

    const int S = K / BKG;
    stage_presplit(Ah, Al, Bh, Bl, K, m0, n0, 0, buf, buf + 16384, tid);
    __syncthreads();

    for (int s = 0; s < S; s++) {
        char* cur = buf + (size_t)(s & 1) * GSTAGE;
        if (s + 1 < S) {
            char* nxt = buf + (size_t)((s + 1) & 1) * GSTAGE;
            stage_presplit(Ah, Al, Bh, Bl, K, m0, n0, (s + 1) * BKG,
                           nxt, nxt + 16384, tid);
        }
        uint32_t As_b = smem_u32(cur);
        uint32_t Bs_b = smem_u32(cur + 16384);

#pragma unroll
        for (int ks = 0; ks < 2; ks++) {
            uint32_t ah[4][4], al[4][4];
#pragma unroll
            for (int mt = 0; mt < 4; mt++) {
                int row = wm * 64 + mt * 16 + (lane & 15);
                int ch  = ks * 2 + (lane >> 4);
                ldsm_x4(As_b + (uint32_t)row * 128 + (uint32_t)((ch ^ (row & 7)) << 4), ah[mt]);
                ldsm_x4(As_b + (uint32_t)row * 128 + (uint32_t)(((ch + 4) ^ (row & 7)) << 4), al[mt]);
            }
#pragma unroll
            for (int np = 0; np < 2; np++) {
                int g    = lane >> 3;
                int nrow = wn * 32 + np * 16 + ((g >> 1) << 3) + (lane & 7);
                int ch   = ks * 2 + (g & 1);
                uint32_t bh[4], bl[4];
                ldsm_x4(Bs_b + (uint32_t)nrow * 128 + (uint32_t)((ch ^ (nrow & 7)) << 4), bh);
                ldsm_x4(Bs_b + (uint32_t)nrow * 128 + (uint32_t)(((ch + 4) ^ (nrow & 7)) << 4), bl);
#pragma unroll
                for (int j = 0; j < 2; j++) {
                    int nt = np * 2 + j;
#pragma unroll
                    for (int mt = 0; mt < 4; mt++) {
                        mma_bf16(acc[mt][nt], ah[mt], &bh[2 * j]);
                        mma_bf16(acc[mt][nt], ah[mt], &bl[2 * j]);
                        mma_bf16(acc[mt][nt], al[mt], &bh[2 * j]);
                    }
                }
            }
        }
        __syncthreads();
    }

    const int rbase = m0 + wm * 64 + (lane >> 2);
    const int cbase = n0 + wn * 32 + (lane & 3) * 2;
#pragma unroll
    for (int mt = 0; mt < 4; mt++) {
#pragma unroll
        for (int nt = 0; nt < 4; nt++) {
            int r0 = rbase + mt * 16;
            int r1 = r0 + 8;
            int c  = cbase + nt * 8;
            float a0 = acc[mt][nt][0], a1 = acc[mt][nt][1];
            float a2 = acc[mt][nt][2], a3 = acc[mt][nt][3];
            if (mode == 0) {
                *(float2*)(C + (size_t)r0 * N + c) = make_float2(a0, a1);
                *(float2*)(C + (size_t)r1 * N + c) = make_float2(a2, a3);
            } else if (mode == 1) {
                int i  = (c & 63) >> 1;
                int t0 = r0 & (T_ - 1);
                int t1 = r1 & (T_ - 1);
                float cs0 = fc[t0 * 32 + i], sn0 = fs[t0 * 32 + i];
                float cs1 = fc[t1 * 32 + i], sn1 = fs[t1 * 32 + i];
                float u0 = (a0 * cs0 - a1 * sn0) * oscale;
                float u1 = (a0 * sn0 + a1 * cs0) * oscale;
                float v0 = (a2 * cs1 - a3 * sn1) * oscale;
                float v1 = (a2 * sn1 + a3 * cs1) * oscale;
                __nv_bfloat16 h0, h1, h2, h3, l0, l1, l2, l3;
                split1(u0, h0, l0); split1(u1, h1, l1);
                split1(v0, h2, l2); split1(v1, h3, l3);
                *(uint32_t*)(outh + (size_t)r0 * N + c) = packbf2(h0, h1);
                *(uint32_t*)(outl + (size_t)r0 * N + c) = packbf2(l0, l1);
                *(uint32_t*)(outh + (size_t)r1 * N + c) = packbf2(h2, h3);
                *(uint32_t*)(outl + (size_t)r1 * N + c) = packbf2(l2, l3);
            } else {
                __nv_bfloat16 h, l;
                split1(a0, h, l);
                outh[(size_t)c * M_ + r0] = h;       outl[(size_t)c * M_ + r0] = l;
                split1(a1, h, l);
                outh[(size_t)(c + 1) * M_ + r0] = h; outl[(size_t)(c + 1) * M_ + r0] = l;
                split1(a2, h, l);
                outh[(size_t)c * M_ + r1] = h;       outl[(size_t)c * M_ + r1] = l;
                split1(a3, h, l);
                outh[(size_t)(c + 1) * M_ + r1] = h; outl[(size_t)(c + 1) * M_ + r1] = l;
            }
        }
    }
}

// Fused QKV projection + RoPE + split (+ V transpose)
__global__ __launch_bounds__(256, 1)
void tc_qkv_kernel(const float* __restrict__ fc, const float* __restrict__ fs) {
    extern __shared__ char dynq[];
    const int xb = blockIdx.x;
    const int mb = blockIdx.y;
    if (xb < 16) {
        tc_gemm_tile(g_xh, g_xl, g_wqt_h, g_wqt_l, DIM_, KDEPTH_, mb * 128, xb * 128,
                     dynq, 1, nullptr, g_qh, g_ql, fc, fs, 0.125f);
    } else if (xb < 20) {
        tc_gemm_tile(g_xh, g_xl, g_wkt_h, g_wkt_l, KVD_, KDEPTH_, mb * 128, (xb - 16) * 128,
                     dynq, 1, nullptr, g_kh, g_kl, fc, fs, 1.0f);
    } else {
        tc_gemm_tile(g_xh, g_xl, g_wvt_h, g_wvt_l, KVD_, KDEPTH_, mb * 128, (xb - 20) * 128,
                     dynq, 2, nullptr, g_vth, g_vtl, nullptr, nullptr, 1.0f);
    }
}

__global__ __launch_bounds__(256, 1)
void tc_out_kernel(float* __restrict__ out) {
    extern __shared__ char dyno[];
    tc_gemm_tile(g_atth, g_attl, g_wot_h, g_wot_l, DIM_, DIM_,
                 blockIdx.y * 128, blockIdx.x * 128,
                 dyno, 0, out, nullptr, nullptr, nullptr, nullptr, 1.0f);
}

// ---------------------------------------------------------------------------
// Tensor-core flash attention (causal, GQA), bf16 3-term split.
// Round-4 proven core; epilogue writes bf16 hi/lo. 4 warps, smem 48KB.
// ---------------------------------------------------------------------------
#define ATTN_SMEM_BYTES (48 * 1024)

__global__ __launch_bounds__(128)
void attn_mma_kernel() {
    extern __shared__ char sm[];
    char* sQh = sm;
    char* sQl = sm + 8192;
    char* sKh = sm + 16384;
    char* sKl = sm + 24576;
    char* sVh = sm + 32768;
    char* sVl = sm + 40960;

    const int qt = blockIdx.x;
    const int h  = blockIdx.y;
    const int b  = blockIdx.z;
    const int g  = h >> 2;
    const int tid  = threadIdx.x;
    const int w    = tid >> 5;
    const int lane = tid & 31;
    const int q0 = qt * 64;

    // ---- stage Q tile (hi/lo) ----
    {
        const __nv_bfloat16* qh_g = g_qh + (size_t)(b * T_ + q0) * DIM_ + h * HD_;
        const __nv_bfloat16* ql_g = g_ql + (size_t)(b * T_ + q0) * DIM_ + h * HD_;
#pragma unroll
        for (int it = 0; it < 4; it++) {
            int idx = it * 128 + tid;
            int row = idx >> 3;
            int c4  = idx & 7;
            uint32_t soff = (uint32_t)row * 128 + (uint32_t)((c4 ^ (row & 7)) << 4);
            *(uint4*)(sQh + soff) = *(const uint4*)(qh_g + (size_t)row * DIM_ + c4 * 8);
            *(uint4*)(sQl + soff) = *(const uint4*)(ql_g + (size_t)row * DIM_ + c4 * 8);
        }
    }
    __syncthreads();

    // ---- load Q fragments (persistent in registers) ----
    uint32_t qh[4][4], ql[4][4];
    {
        uint32_t Qh_b = smem_u32(sQh);
        uint32_t Ql_b = smem_u32(sQl);
        int row = w * 16 + (lane & 15);
        int chb = lane >> 4;
#pragma unroll
        for (int kf = 0; kf < 4; kf++) {
            int ch = kf * 2 + chb;
            uint32_t off = (uint32_t)row * 128 + (uint32_t)((ch ^ (row & 7)) << 4);
            ldsm_x4(Qh_b + off, qh[kf]);
            ldsm_x4(Ql_b + off, ql[kf]);
        }
    }

    float o[8][4];
#pragma unroll
    for (int dt = 0; dt < 8; dt++)
#pragma unroll
        for (int q = 0; q < 4; q++) o[dt][q] = 0.f;
    float m0 = -INFINITY, m1 = -INFINITY, l0 = 0.f, l1 = 0.f;

    const uint32_t Kh_b = smem_u32(sKh);
    const uint32_t Kl_b = smem_u32(sKl);
    const uint32_t Vh_b = smem_u32(sVh);
    const uint32_t Vl_b = smem_u32(sVl);

    const int rg0 = q0 + w * 16 + (lane >> 2);
    const int rg1 = rg0 + 8;

    for (int kt = 0; kt <= qt; kt++) {
        __syncthreads();
        {
            const __nv_bfloat16* kh_g = g_kh + (size_t)(b * T_ + kt * 64) * KVD_ + g * HD_;
            const __nv_bfloat16* kl_g = g_kl + (size_t)(b * T_ + kt * 64) * KVD_ + g * HD_;
            const __nv_bfloat16* vh_g = g_vth + (size_t)(g * HD_) * M_ + b * T_ + kt * 64;
            const __nv_bfloat16* vl_g = g_vtl + (size_t)(g * HD_) * M_ + b * T_ + kt * 64;
#pragma unroll
            for (int it = 0; it < 4; it++) {
                int idx = it * 128 + tid;
                int row = idx >> 3;
                int c4  = idx & 7;
                uint32_t soff = (uint32_t)row * 128 + (uint32_t)((c4 ^ (row & 7)) << 4);
                *(uint4*)(sKh + soff) = *(const uint4*)(kh_g + (size_t)row * KVD_ + c4 * 8);
                *(uint4*)(sKl + soff) = *(const uint4*)(kl_g + (size_t)row * KVD_ + c4 * 8);
                *(uint4*)(sVh + soff) = *(const uint4*)(vh_g + (size_t)row * M_ + c4 * 8);
                *(uint4*)(sVl + soff) = *(const uint4*)(vl_g + (size_t)row * M_ + c4 * 8);
            }
        }
        __syncthreads();

        // ---- S = Q K^T (3-term split) ----
        float s[8][4];
#pragma unroll
        for (int nt = 0; nt < 8; nt++)
#pragma unroll
            for (int q = 0; q < 4; q++) s[nt][q] = 0.f;

#pragma unroll
        for (int kf = 0; kf < 4; kf++) {
#pragma unroll
            for (int np = 0; np < 4; np++) {
                int gg   = lane >> 3;
                int nrow = np * 16 + ((gg >> 1) << 3) + (lane & 7);
                int ch   = kf * 2 + (gg & 1);
                uint32_t off = (uint32_t)nrow * 128 + (uint32_t)((ch ^ (nrow & 7)) << 4);
                uint32_t bh[4], bl[4];
                ldsm_x4(Kh_b + off, bh);
                ldsm_x4(Kl_b + off, bl);
#pragma unroll
                for (int j = 0; j < 2; j++) {
                    int nt = np * 2 + j;
                    mma_bf16(s[nt], qh[kf], &bh[2 * j]);
                    mma_bf16(s[nt], qh[kf], &bl[2 * j]);
                    mma_bf16(s[nt], ql[kf], &bh[2 * j]);
                }
            }
        }

        if (kt == qt) {
            int cb = kt * 64 + (lane & 3) * 2;
#pragma unroll
            for (int nt = 0; nt < 8; nt++) {
                int c = cb + nt * 8;
                if (c > rg0)     s[nt][0] = -INFINITY;
                if (c + 1 > rg0) s[nt][1] = -INFINITY;
                if (c > rg1)     s[nt][2] = -INFINITY;
                if (c + 1 > rg1) s[nt][3] = -INFINITY;
            }
        }

        float mx0 = s[0][0], mx1 = s[0][2];
#pragma unroll
        for (int nt = 0; nt < 8; nt++) {
            mx0 = fmaxf(mx0, fmaxf(s[nt][0], s[nt][1]));
            mx1 = fmaxf(mx1, fmaxf(s[nt][2], s[nt][3]));
        }
        mx0 = fmaxf(mx0, __shfl_xor_sync(0xffffffffu, mx0, 1));
        mx0 = fmaxf(mx0, __shfl_xor_sync(0xffffffffu, mx0, 2));
        mx1 = fmaxf(mx1, __shfl_xor_sync(0xffffffffu, mx1, 1));
        mx1 = fmaxf(mx1, __shfl_xor_sync(0xffffffffu, mx1, 2));

        float mn0 = fmaxf(fmaxf(m0, mx0), -1e30f);
        float mn1 = fmaxf(fmaxf(m1, mx1), -1e30f);
        float a0 = __expf(m0 - mn0);
        float a1 = __expf(m1 - mn1);
        m0 = mn0; m1 = mn1;

        float sum0 = 0.f, sum1 = 0.f;
#pragma unroll
        for (int nt = 0; nt < 8; nt++) {
            s[nt][0] = __expf(s[nt][0] - mn0);
            s[nt][1] = __expf(s[nt][1] - mn0);
            s[nt][2] = __expf(s[nt][2] - mn1);
            s[nt][3] = __expf(s[nt][3] - mn1);
            sum0 += s[nt][0] + s[nt][1];
            sum1 += s[nt][2] + s[nt][3];
        }
        sum0 += __shfl_xor_sync(0xffffffffu, sum0, 1);
        sum0 += __shfl_xor_sync(0xffffffffu, sum0, 2);
        sum1 += __shfl_xor_sync(0xffffffffu, sum1, 1);
        sum1 += __shfl_xor_sync(0xffffffffu, sum1, 2);
        l0 = l0 * a0 + sum0;
        l1 = l1 * a1 + sum1;

#pragma unroll
        for (int dt = 0; dt < 8; dt++) {
            o[dt][0] *= a0; o[dt][1] *= a0;
            o[dt][2] *= a1; o[dt][3] *= a1;
        }

        // ---- O += P V (3-term split) ----
#pragma unroll
        for (int kf = 0; kf < 4; kf++) {
            uint32_t aph[4], apl[4];
#pragma unroll
            for (int half = 0; half < 2; half++) {
                float p0 = s[2 * kf + half][0], p1 = s[2 * kf + half][1];
                float p2 = s[2 * kf + half][2], p3 = s[2 * kf + half][3];
                __nv_bfloat16 h0, h1, h2, h3, e0, e1, e2, e3;
                split1(p0, h0, e0); split1(p1, h1, e1);
                split1(p2, h2, e2); split1(p3, h3, e3);
                aph[2 * half]     = packbf2(h0, h1);
                aph[2 * half + 1] = packbf2(h2, h3);
                apl[2 * half]     = packbf2(e0, e1);
                apl[2 * half + 1] = packbf2(e2, e3);
            }
#pragma unroll
            for (int dp = 0; dp < 4; dp++) {
                int gg   = lane >> 3;
                int drow = dp * 16 + ((gg >> 1) << 3) + (lane & 7);
                int ch   = kf * 2 + (gg & 1);
                uint32_t off = (uint32_t)drow * 128 + (uint32_t)((ch ^ (drow & 7)) << 4);
                uint32_t vh[4], vl[4];
                ldsm_x4(Vh_b + off, vh);
                ldsm_x4(Vl_b + off, vl);
#pragma unroll
                for (int j = 0; j < 2; j++) {
                    int dt = dp * 2 + j;
                    mma_bf16(o[dt], aph, &vh[2 * j]);
                    mma_bf16(o[dt], aph, &vl[2 * j]);
                    mma_bf16(o[dt], apl, &vh[2 * j]);
                }
            }
        }
    }

    // ---- epilogue: split to bf16 hi/lo for the out-projection ----
    float inv0 = 1.f / l0;
    float inv1 = 1.f / l1;
    size_t o0 = (size_t)(b * T_ + rg0) * DIM_ + h * HD_ + (lane & 3) * 2;
    size_t o1 = (size_t)(b * T_ + rg1) * DIM_ + h * HD_ + (lane & 3) * 2;
#pragma unroll
    for (int dt = 0; dt < 8; dt++) {
        __nv_bfloat16 h0, h1, h2, h3, e0, e1, e2, e3;
        split1(o[dt][0] * inv0, h0, e0);
        split1(o[dt][1] * inv0, h1, e1);
        split1(o[dt][2] * inv1, h2, e2);
        split1(o[dt][3] * inv1, h3, e3);
        *(uint32_t*)(g_atth + o0 + dt * 8) = packbf2(h0, h1);
        *(uint32_t*)(g_attl + o0 + dt * 8) = packbf2(e0, e1);
        *(uint32_t*)(g_atth + o1 + dt * 8) = packbf2(h2, h3);
        *(uint32_t*)(g_attl + o1 + dt * 8) = packbf2(e2, e3);
    }
}

// ---------------------------------------------------------------------------
// Launcher
// ---------------------------------------------------------------------------
extern "C" void kernel_launch(void* const* d_in, const int* in_sizes, int n_in,
                              void* d_out, int out_size) {
    const float* x  = (const float*)d_in[0];
    const float* fc = (const float*)d_in[1];
    const float* fs = (const float*)d_in[2];
    const float* wq = (const float*)d_in[3];
    const float* wk = (const float*)d_in[4];
    const float* wv = (const float*)d_in[5];
    const float* wo = (const float*)d_in[6];
    float* out = (float*)d_out;

    cudaFuncSetAttribute(tc_qkv_kernel,
                         cudaFuncAttributeMaxDynamicSharedMemorySize, GEMM_SMEM_BYTES);
    cudaFuncSetAttribute(tc_out_kernel,
                         cudaFuncAttributeMaxDynamicSharedMemorySize, GEMM_SMEM_BYTES);
    cudaFuncSetAttribute(attn_mma_kernel,
                         cudaFuncAttributeMaxDynamicSharedMemorySize, ATTN_SMEM_BYTES);

    // 0) Prepass: split x; transpose+split weights (dest resolved in device code)
    split_x_kernel<<<(M_ * DIM_ / 4) / 256, 256>>>(x);
    tsplit_kernel<<<dim3(DIM_ / 32, DIM_ / 32), dim3(32, 8)>>>(wq, 0, DIM_, DIM_);
    tsplit_kernel<<<dim3(KVD_ / 32, DIM_ / 32), dim3(32, 8)>>>(wk, 1, DIM_, KVD_);
    tsplit_kernel<<<dim3(KVD_ / 32, DIM_ / 32), dim3(32, 8)>>>(wv, 2, DIM_, KVD_);
    tsplit_kernel<<<dim3(DIM_ / 32, DIM_ / 32), dim3(32, 8)>>>(wo, 3, DIM_, DIM_);

    // 1) QKV projections + fused RoPE + split (+ V transpose)
    tc_qkv_kernel<<<dim3(24, 32), 256, GEMM_SMEM_BYTES>>>(fc, fs);

    // 2) Tensor-core causal GQA flash attention
    attn_mma_kernel<<<dim3(T_ / 64, H_, B_), 128, ATTN_SMEM_BYTES>>>();

    // 3) Output projection
    tc_out_kernel<<<dim3(16, 32), 256, GEMM_SMEM_BYTES>>>(out);
}

// round 9
// speedup vs baseline: 5.8628x; 1.2411x over previous
#include <cuda_runtime.h>
#include <cuda_bf16.h>
#include <math.h>
#include <stdint.h>

// Problem constants
#define B_   2
#define T_   2048
#define DIM_ 2048
#define H_   32
#define HKV_ 8
#define HD_  64
#define M_   (B_ * T_)            // 4096
#define KVD_ (HKV_ * HD_)         // 512
#define KDEPTH_ 2048

// ---------------------------------------------------------------------------
// Scratch (device globals; no allocation allowed)
// ---------------------------------------------------------------------------
__device__ __nv_bfloat16 g_xh[(size_t)M_ * DIM_];
__device__ __nv_bfloat16 g_xl[(size_t)M_ * DIM_];
__device__ __nv_bfloat16 g_wqt_h[(size_t)DIM_ * DIM_];   // [n][k]
__device__ __nv_bfloat16 g_wqt_l[(size_t)DIM_ * DIM_];
__device__ __nv_bfloat16 g_wkt_h[(size_t)KVD_ * DIM_];
__device__ __nv_bfloat16 g_wkt_l[(size_t)KVD_ * DIM_];
__device__ __nv_bfloat16 g_wvt_h[(size_t)KVD_ * DIM_];
__device__ __nv_bfloat16 g_wvt_l[(size_t)KVD_ * DIM_];
__device__ __nv_bfloat16 g_wot_h[(size_t)DIM_ * DIM_];
__device__ __nv_bfloat16 g_wot_l[(size_t)DIM_ * DIM_];

__device__ __nv_bfloat16 g_qh[(size_t)M_ * DIM_];   // rope'd, pre-scaled Q
__device__ __nv_bfloat16 g_ql[(size_t)M_ * DIM_];
__device__ __nv_bfloat16 g_kh[(size_t)M_ * KVD_];
__device__ __nv_bfloat16 g_kl[(size_t)M_ * KVD_];
__device__ __nv_bfloat16 g_vth[(size_t)KVD_ * M_];  // V transposed [d][t]
__device__ __nv_bfloat16 g_vtl[(size_t)KVD_ * M_];
__device__ __nv_bfloat16 g_atth[(size_t)M_ * DIM_]; // attention out hi/lo
__device__ __nv_bfloat16 g_attl[(size_t)M_ * DIM_];

// ---------------------------------------------------------------------------
// Helpers
// ---------------------------------------------------------------------------
__device__ __forceinline__ uint32_t smem_u32(const void* p) {
    uint32_t a;
    asm("{ .reg .u64 t; cvta.to.shared.u64 t, %1; cvt.u32.u64 %0, t; }"
        : "=r"(a) : "l"(p));
    return a;
}
__device__ __forceinline__ uint32_t packbf2(__nv_bfloat16 a, __nv_bfloat16 b) {
    return ((uint32_t)__bfloat16_as_ushort(b) << 16) | (uint32_t)__bfloat16_as_ushort(a);
}
__device__ __forceinline__ void ldsm_x4(uint32_t addr, uint32_t* r) {
    asm volatile("ldmatrix.sync.aligned.m8n8.x4.shared.b16 {%0,%1,%2,%3}, [%4];"
                 : "=r"(r[0]), "=r"(r[1]), "=r"(r[2]), "=r"(r[3]) : "r"(addr));
}
__device__ __forceinline__ void mma_bf16(float* c, const uint32_t* a, const uint32_t* b) {
    asm volatile(
        "mma.sync.aligned.m16n8k16.row.col.f32.bf16.bf16.f32 "
        "{%0,%1,%2,%3}, {%4,%5,%6,%7}, {%8,%9}, {%0,%1,%2,%3};"
        : "+f"(c[0]), "+f"(c[1]), "+f"(c[2]), "+f"(c[3])
        : "r"(a[0]), "r"(a[1]), "r"(a[2]), "r"(a[3]), "r"(b[0]), "r"(b[1]));
}
__device__ __forceinline__ void split1(float v, __nv_bfloat16& h, __nv_bfloat16& l) {
    h = __float2bfloat16_rn(v);
    l = __float2bfloat16_rn(v - __bfloat162float(h));
}
__device__ __forceinline__ void cp16(uint32_t s, const void* g) {
    asm volatile("cp.async.ca.shared.global [%0], [%1], 16;" :: "r"(s), "l"(g) : "memory");
}
#define CP_COMMIT() asm volatile("cp.async.commit_group;" ::: "memory")
#define CP_WAIT(n)  asm volatile("cp.async.wait_group %0;" :: "n"(n) : "memory")

// ---------------------------------------------------------------------------
// Prepass: split x, transpose+split weights.
// Destination __device__ globals resolved INSIDE device code (host-side
// symbol args are the HOST shadow address — the r5-r7 silent-zero bug).
// ---------------------------------------------------------------------------
__global__ void split_x_kernel(const float* __restrict__ x) {
    size_t idx = (size_t)blockIdx.x * 256 + threadIdx.x;
    float4 v = ((const float4*)x)[idx];
    __nv_bfloat16 hx, hy, hz, hw, lx, ly, lz, lw;
    split1(v.x, hx, lx); split1(v.y, hy, ly);
    split1(v.z, hz, lz); split1(v.w, hw, lw);
    *(uint2*)(g_xh + idx * 4) = make_uint2(packbf2(hx, hy), packbf2(hz, hw));
    *(uint2*)(g_xl + idx * 4) = make_uint2(packbf2(lx, ly), packbf2(lz, lw));
}

__global__ void tsplit_kernel(const float* __restrict__ src, int which,
                              int K, int N) {   // src [K,N] -> dst [N,K]
    __nv_bfloat16* dsth;
    __nv_bfloat16* dstl;
    if (which == 0)      { dsth = g_wqt_h; dstl = g_wqt_l; }
    else if (which == 1) { dsth = g_wkt_h; dstl = g_wkt_l; }
    else if (which == 2) { dsth = g_wvt_h; dstl = g_wvt_l; }
    else                 { dsth = g_wot_h; dstl = g_wot_l; }

    __shared__ float tile[32][33];
    int n0 = blockIdx.x * 32, k0 = blockIdx.y * 32;
    int tx = threadIdx.x, ty = threadIdx.y;
#pragma unroll
    for (int i = 0; i < 4; i++)
        tile[ty + i * 8][tx] = src[(size_t)(k0 + ty + i * 8) * N + n0 + tx];
    __syncthreads();
#pragma unroll
    for (int i = 0; i < 4; i++) {
        float v = tile[tx][ty + i * 8];
        __nv_bfloat16 h, l;
        split1(v, h, l);
        dsth[(size_t)(n0 + ty + i * 8) * K + k0 + tx] = h;
        dstl[(size_t)(n0 + ty + i * 8) * K + k0 + tx] = l;
    }
}

// ---------------------------------------------------------------------------
// Pipelined HMMA bf16 (3-term split) GEMM: 128x128 tile, BK=32, 3 cp.async
// stages, ALWAYS-COMMIT (tail-exact group counting). Pre-split bf16 inputs.
// smem/stage 32KB; total 96KB dynamic smem.
// ---------------------------------------------------------------------------
#define BKG 32
#define GSTAGE 32768
#define GEMM_SMEM_BYTES (3 * GSTAGE)

__device__ __forceinline__ void gemm_issue(const __nv_bfloat16* __restrict__ Ah,
                                           const __nv_bfloat16* __restrict__ Al,
                                           const __nv_bfloat16* __restrict__ Bh,
                                           const __nv_bfloat16* __restrict__ Bl,
                                           int K, int m0, int n0, int k0,
                                           uint32_t As, uint32_t Bs, int tid) {
#pragma unroll
    for (int it = 0; it < 4; it++) {
        int idx = it * 256 + tid;
        int r = idx >> 3, c = idx & 7;
        const __nv_bfloat16* src = (c < 4)
            ? (Ah + (size_t)(m0 + r) * K + k0 + c * 8)
            : (Al + (size_t)(m0 + r) * K + k0 + (c - 4) * 8);
        cp16(As + (uint32_t)r * 128 + (uint32_t)((c ^ (r & 7)) << 4), src);
    }
#pragma unroll
    for (int it = 0; it < 4; it++) {
        int idx = it * 256 + tid;
        int r = idx >> 3, c = idx & 7;
        const __nv_bfloat16* src = (c < 4)
            ? (Bh + (size_t)(n0 + r) * K + k0 + c * 8)
            : (Bl + (size_t)(n0 + r) * K + k0 + (c - 4) * 8);
        cp16(Bs + (uint32_t)r * 128 + (uint32_t)((c ^ (r & 7)) << 4), src);
    }
}

__device__ __forceinline__ void tc_gemm_pipe(const __nv_bfloat16* __restrict__ Ah,
                                             const __nv_bfloat16* __restrict__ Al,
                                             const __nv_bfloat16* __restrict__ Bh,
                                             const __nv_bfloat16* __restrict__ Bl,
                                             int N, int K, int m0, int n0,
                                             char* buf, int mode,
                                             float* __restrict__ C,
                                             __nv_bfloat16* __restrict__ outh,
                                             __nv_bfloat16* __restrict__ outl,
                                             const float* __restrict__ fc,
                                             const float* __restrict__ fs,
                                             float oscale) {
    const int tid  = threadIdx.x;
    const int wid  = tid >> 5;
    const int lane = tid & 31;
    const int wm = wid >> 2;
    const int wn = wid & 3;
    const uint32_t sb = smem_u32(buf);

    float acc[4][4][4];
#pragma unroll
    for (int i = 0; i < 4; i++)
#pragma unroll
        for (int j = 0; j < 4; j++)
#pragma unroll
            for (int q = 0; q < 4; q++) acc[i][j][q] = 0.f;

    const int S = K / BKG;
    // prologue: stages 0,1 in flight (one commit group each)
    gemm_issue(Ah, Al, Bh, Bl, K, m0, n0, 0, sb, sb + 16384, tid);
    CP_COMMIT();
    gemm_issue(Ah, Al, Bh, Bl, K, m0, n0, BKG, sb + GSTAGE, sb + GSTAGE + 16384, tid);
    CP_COMMIT();

    for (int s = 0; s < S; s++) {
        __syncthreads();   // all warps done reading buffer (s+2)%3 (from stage s-1)
        if (s + 2 < S) {
            int bi = (s + 2) % 3;
            gemm_issue(Ah, Al, Bh, Bl, K, m0, n0, (s + 2) * BKG,
                       sb + bi * GSTAGE, sb + bi * GSTAGE + 16384, tid);
        }
        CP_COMMIT();       // always commit (empty tail groups keep count exact)
        CP_WAIT(2);        // all but 2 newest groups done -> stage s arrived
        __syncthreads();

        uint32_t As_b = sb + (uint32_t)(s % 3) * GSTAGE;
        uint32_t Bs_b = As_b + 16384;

#pragma unroll
        for (int ks = 0; ks < 2; ks++) {
            uint32_t ah[4][4], al[4][4];
#pragma unroll
            for (int mt = 0; mt < 4; mt++) {
                int row = wm * 64 + mt * 16 + (lane & 15);
                int ch  = ks * 2 + (lane >> 4);
                ldsm_x4(As_b + (uint32_t)row * 128 + (uint32_t)((ch ^ (row & 7)) << 4), ah[mt]);
                ldsm_x4(As_b + (uint32_t)row * 128 + (uint32_t)(((ch + 4) ^ (row & 7)) << 4), al[mt]);
            }
#pragma unroll
            for (int np = 0; np < 2; np++) {
                int g    = lane >> 3;
                int nrow = wn * 32 + np * 16 + ((g >> 1) << 3) + (lane & 7);
                int ch   = ks * 2 + (g & 1);
                uint32_t bh[4], bl[4];
                ldsm_x4(Bs_b + (uint32_t)nrow * 128 + (uint32_t)((ch ^ (nrow & 7)) << 4), bh);
                ldsm_x4(Bs_b + (uint32_t)nrow * 128 + (uint32_t)(((ch + 4) ^ (nrow & 7)) << 4), bl);
#pragma unroll
                for (int j = 0; j < 2; j++) {
                    int nt = np * 2 + j;
#pragma unroll
                    for (int mt = 0; mt < 4; mt++) {
                        mma_bf16(acc[mt][nt], ah[mt], &bh[2 * j]);
                        mma_bf16(acc[mt][nt], ah[mt], &bl[2 * j]);
                        mma_bf16(acc[mt][nt], al[mt], &bh[2 * j]);
                    }
                }
            }
        }
    }

    const int rbase = m0 + wm * 64 + (lane >> 2);
    const int cbase = n0 + wn * 32 + (lane & 3) * 2;
#pragma unroll
    for (int mt = 0; mt < 4; mt++) {
#pragma unroll
        for (int nt = 0; nt < 4; nt++) {
            int r0 = rbase + mt * 16;
            int r1 = r0 + 8;
            int c  = cbase + nt * 8;
            float a0 = acc[mt][nt][0], a1 = acc[mt][nt][1];
            float a2 = acc[mt][nt][2], a3 = acc[mt][nt][3];
            if (mode == 0) {
                *(float2*)(C + (size_t)r0 * N + c) = make_float2(a0, a1);
                *(float2*)(C + (size_t)r1 * N + c) = make_float2(a2, a3);
            } else if (mode == 1) {
                int i  = (c & 63) >> 1;
                int t0 = r0 & (T_ - 1);
                int t1 = r1 & (T_ - 1);
                float cs0 = fc[t0 * 32 + i], sn0 = fs[t0 * 32 + i];
                float cs1 = fc[t1 * 32 + i], sn1 = fs[t1 * 32 + i];
                float u0 = (a0 * cs0 - a1 * sn0) * oscale;
                float u1 = (a0 * sn0 + a1 * cs0) * oscale;
                float v0 = (a2 * cs1 - a3 * sn1) * oscale;
                float v1 = (a2 * sn1 + a3 * cs1) * oscale;
                __nv_bfloat16 h0, h1, h2, h3, l0, l1, l2, l3;
                split1(u0, h0, l0); split1(u1, h1, l1);
                split1(v0, h2, l2); split1(v1, h3, l3);
                *(uint32_t*)(outh + (size_t)r0 * N + c) = packbf2(h0, h1);
                *(uint32_t*)(outl + (size_t)r0 * N + c) = packbf2(l0, l1);
                *(uint32_t*)(outh + (size_t)r1 * N + c) = packbf2(h2, h3);
                *(uint32_t*)(outl + (size_t)r1 * N + c) = packbf2(l2, l3);
            } else {
                __nv_bfloat16 h, l;
                split1(a0, h, l);
                outh[(size_t)c * M_ + r0] = h;       outl[(size_t)c * M_ + r0] = l;
                split1(a1, h, l);
                outh[(size_t)(c + 1) * M_ + r0] = h; outl[(size_t)(c + 1) * M_ + r0] = l;
                split1(a2, h, l);
                outh[(size_t)c * M_ + r1] = h;       outl[(size_t)c * M_ + r1] = l;
                split1(a3, h, l);
                outh[(size_t)(c + 1) * M_ + r1] = h; outl[(size_t)(c + 1) * M_ + r1] = l;
            }
        }
    }
}

// Fused QKV projection + RoPE + split (+ V transpose)
__global__ __launch_bounds__(256, 1)
void tc_qkv_kernel(const float* __restrict__ fc, const float* __restrict__ fs) {
    extern __shared__ char dynq[];
    const int xb = blockIdx.x;
    const int mb = blockIdx.y;
    if (xb < 16) {
        tc_gemm_pipe(g_xh, g_xl, g_wqt_h, g_wqt_l, DIM_, KDEPTH_, mb * 128, xb * 128,
                     dynq, 1, nullptr, g_qh, g_ql, fc, fs, 0.125f);
    } else if (xb < 20) {
        tc_gemm_pipe(g_xh, g_xl, g_wkt_h, g_wkt_l, KVD_, KDEPTH_, mb * 128, (xb - 16) * 128,
                     dynq, 1, nullptr, g_kh, g_kl, fc, fs, 1.0f);
    } else {
        tc_gemm_pipe(g_xh, g_xl, g_wvt_h, g_wvt_l, KVD_, KDEPTH_, mb * 128, (xb - 20) * 128,
                     dynq, 2, nullptr, g_vth, g_vtl, nullptr, nullptr, 1.0f);
    }
}

__global__ __launch_bounds__(256, 1)
void tc_out_kernel(float* __restrict__ out) {
    extern __shared__ char dyno[];
    tc_gemm_pipe(g_atth, g_attl, g_wot_h, g_wot_l, DIM_, DIM_,
                 blockIdx.y * 128, blockIdx.x * 128,
                 dyno, 0, out, nullptr, nullptr, nullptr, nullptr, 1.0f);
}

// ---------------------------------------------------------------------------
// Tensor-core flash attention (causal, GQA), bf16 3-term split.
// cp.async + double-buffered K/V stages. 4 warps.
// smem: Qh/Ql 8KB each + 2 KV stages x 32KB = 80KB.
// ---------------------------------------------------------------------------
#define ATTN_SMEM_BYTES (80 * 1024)
#define KVSTAGE 32768

__device__ __forceinline__ void attn_issue_kv(char* base,
                                              const __nv_bfloat16* kh_g,
                                              const __nv_bfloat16* kl_g,
                                              const __nv_bfloat16* vh_g,
                                              const __nv_bfloat16* vl_g,
                                              int kt, int tid) {
    uint32_t sKh = smem_u32(base);
    uint32_t sKl = sKh + 8192;
    uint32_t sVh = sKh + 16384;
    uint32_t sVl = sKh + 24576;
    const __nv_bfloat16* kh = kh_g + (size_t)(kt * 64) * KVD_;
    const __nv_bfloat16* kl = kl_g + (size_t)(kt * 64) * KVD_;
    const __nv_bfloat16* vh = vh_g + kt * 64;
    const __nv_bfloat16* vl = vl_g + kt * 64;
#pragma unroll
    for (int it = 0; it < 4; it++) {
        int idx = it * 128 + tid;
        int row = idx >> 3;
        int c4  = idx & 7;
        uint32_t soff = (uint32_t)row * 128 + (uint32_t)((c4 ^ (row & 7)) << 4);
        cp16(sKh + soff, kh + (size_t)row * KVD_ + c4 * 8);
        cp16(sKl + soff, kl + (size_t)row * KVD_ + c4 * 8);
        cp16(sVh + soff, vh + (size_t)row * M_ + c4 * 8);
        cp16(sVl + soff, vl + (size_t)row * M_ + c4 * 8);
    }
}

__global__ __launch_bounds__(128)
void attn_mma_kernel() {
    extern __shared__ char sm[];
    char* sQh = sm;
    char* sQl = sm + 8192;
    char* sKV0 = sm + 16384;
    char* sKV1 = sm + 16384 + KVSTAGE;

    const int qt = blockIdx.x;
    const int h  = blockIdx.y;
    const int b  = blockIdx.z;
    const int g  = h >> 2;
    const int tid  = threadIdx.x;
    const int w    = tid >> 5;
    const int lane = tid & 31;
    const int q0 = qt * 64;

    const __nv_bfloat16* kh_g = g_kh + (size_t)(b * T_) * KVD_ + g * HD_;
    const __nv_bfloat16* kl_g = g_kl + (size_t)(b * T_) * KVD_ + g * HD_;
    const __nv_bfloat16* vh_g = g_vth + (size_t)(g * HD_) * M_ + b * T_;
    const __nv_bfloat16* vl_g = g_vtl + (size_t)(g * HD_) * M_ + b * T_;

    // prologue: Q + KV(0) in one commit group
    {
        const __nv_bfloat16* qh_g = g_qh + (size_t)(b * T_ + q0) * DIM_ + h * HD_;
        const __nv_bfloat16* ql_g = g_ql + (size_t)(b * T_ + q0) * DIM_ + h * HD_;
        uint32_t Qh_b = smem_u32(sQh);
        uint32_t Ql_b = smem_u32(sQl);
#pragma unroll
        for (int it = 0; it < 4; it++) {
            int idx = it * 128 + tid;
            int row = idx >> 3;
            int c4  = idx & 7;
            uint32_t soff = (uint32_t)row * 128 + (uint32_t)((c4 ^ (row & 7)) << 4);
            cp16(Qh_b + soff, qh_g + (size_t)row * DIM_ + c4 * 8);
            cp16(Ql_b + soff, ql_g + (size_t)row * DIM_ + c4 * 8);
        }
        attn_issue_kv(sKV0, kh_g, kl_g, vh_g, vl_g, 0, tid);
        CP_COMMIT();
    }

    uint32_t qh[4][4], ql[4][4];
    float o[8][4];
#pragma unroll
    for (int dt = 0; dt < 8; dt++)
#pragma unroll
        for (int q = 0; q < 4; q++) o[dt][q] = 0.f;
    float m0 = -INFINITY, m1 = -INFINITY, l0 = 0.f, l1 = 0.f;

    const int rg0 = q0 + w * 16 + (lane >> 2);
    const int rg1 = rg0 + 8;

    for (int kt = 0; kt <= qt; kt++) {
        CP_WAIT(0);
        __syncthreads();

        if (kt == 0) {   // Q fragments persist in registers
            uint32_t Qh_b = smem_u32(sQh);
            uint32_t Ql_b = smem_u32(sQl);
            int row = w * 16 + (lane & 15);
            int chb = lane >> 4;
#pragma unroll
            for (int kf = 0; kf < 4; kf++) {
                int ch = kf * 2 + chb;
                uint32_t off = (uint32_t)row * 128 + (uint32_t)((ch ^ (row & 7)) << 4);
                ldsm_x4(Qh_b + off, qh[kf]);
                ldsm_x4(Ql_b + off, ql[kf]);
            }
        }
        if (kt + 1 <= qt) {   // prefetch next KV into the other buffer
            attn_issue_kv((kt & 1) ? sKV0 : sKV1, kh_g, kl_g, vh_g, vl_g, kt + 1, tid);
            CP_COMMIT();
        }

        char* kv = (kt & 1) ? sKV1 : sKV0;
        uint32_t Kh_b = smem_u32(kv);
        uint32_t Kl_b = Kh_b + 8192;
        uint32_t Vh_b = Kh_b + 16384;
        uint32_t Vl_b = Kh_b + 24576;

        // ---- S = Q K^T (3-term split) ----
        float s[8][4];
#pragma unroll
        for (int nt = 0; nt < 8; nt++)
#pragma unroll
            for (int q = 0; q < 4; q++) s[nt][q] = 0.f;

#pragma unroll
        for (int kf = 0; kf < 4; kf++) {
#pragma unroll
            for (int np = 0; np < 4; np++) {
                int gg   = lane >> 3;
                int nrow = np * 16 + ((gg >> 1) << 3) + (lane & 7);
                int ch   = kf * 2 + (gg & 1);
                uint32_t off = (uint32_t)nrow * 128 + (uint32_t)((ch ^ (nrow & 7)) << 4);
                uint32_t bh[4], bl[4];
                ldsm_x4(Kh_b + off, bh);
                ldsm_x4(Kl_b + off, bl);
#pragma unroll
                for (int j = 0; j < 2; j++) {
                    int nt = np * 2 + j;
                    mma_bf16(s[nt], qh[kf], &bh[2 * j]);
                    mma_bf16(s[nt], qh[kf], &bl[2 * j]);
                    mma_bf16(s[nt], ql[kf], &bh[2 * j]);
                }
            }
        }

        if (kt == qt) {
            int cb = kt * 64 + (lane & 3) * 2;
#pragma unroll
            for (int nt = 0; nt < 8; nt++) {
                int c = cb + nt * 8;
                if (c > rg0)     s[nt][0] = -INFINITY;
                if (c + 1 > rg0) s[nt][1] = -INFINITY;
                if (c > rg1)     s[nt][2] = -INFINITY;
                if (c + 1 > rg1) s[nt][3] = -INFINITY;
            }
        }

        float mx0 = s[0][0], mx1 = s[0][2];
#pragma unroll
        for (int nt = 0; nt < 8; nt++) {
            mx0 = fmaxf(mx0, fmaxf(s[nt][0], s[nt][1]));
            mx1 = fmaxf(mx1, fmaxf(s[nt][2], s[nt][3]));
        }
        mx0 = fmaxf(mx0, __shfl_xor_sync(0xffffffffu, mx0, 1));
        mx0 = fmaxf(mx0, __shfl_xor_sync(0xffffffffu, mx0, 2));
        mx1 = fmaxf(mx1, __shfl_xor_sync(0xffffffffu, mx1, 1));
        mx1 = fmaxf(mx1, __shfl_xor_sync(0xffffffffu, mx1, 2));

        float mn0 = fmaxf(fmaxf(m0, mx0), -1e30f);
        float mn1 = fmaxf(fmaxf(m1, mx1), -1e30f);
        float a0 = __expf(m0 - mn0);
        float a1 = __expf(m1 - mn1);
        m0 = mn0; m1 = mn1;

        float sum0 = 0.f, sum1 = 0.f;
#pragma unroll
        for (int nt = 0; nt < 8; nt++) {
            s[nt][0] = __expf(s[nt][0] - mn0);
            s[nt][1] = __expf(s[nt][1] - mn0);
            s[nt][2] = __expf(s[nt][2] - mn1);
            s[nt][3] = __expf(s[nt][3] - mn1);
            sum0 += s[nt][0] + s[nt][1];
            sum1 += s[nt][2] + s[nt][3];
        }
        sum0 += __shfl_xor_sync(0xffffffffu, sum0, 1);
        sum0 += __shfl_xor_sync(0xffffffffu, sum0, 2);
        sum1 += __shfl_xor_sync(0xffffffffu, sum1, 1);
        sum1 += __shfl_xor_sync(0xffffffffu, sum1, 2);
        l0 = l0 * a0 + sum0;
        l1 = l1 * a1 + sum1;

#pragma unroll
        for (int dt = 0; dt < 8; dt++) {
            o[dt][0] *= a0; o[dt][1] *= a0;
            o[dt][2] *= a1; o[dt][3] *= a1;
        }

        // ---- O += P V (3-term split) ----
#pragma unroll
        for (int kf = 0; kf < 4; kf++) {
            uint32_t aph[4], apl[4];
#pragma unroll
            for (int half = 0; half < 2; half++) {
                float p0 = s[2 * kf + half][0], p1 = s[2 * kf + half][1];
                float p2 = s[2 * kf + half][2], p3 = s[2 * kf + half][3];
                __nv_bfloat16 h0, h1, h2, h3, e0, e1, e2, e3;
                split1(p0, h0, e0); split1(p1, h1, e1);
                split1(p2, h2, e2); split1(p3, h3, e3);
                aph[2 * half]     = packbf2(h0, h1);
                aph[2 * half + 1] = packbf2(h2, h3);
                apl[2 * half]     = packbf2(e0, e1);
                apl[2 * half + 1] = packbf2(e2, e3);
            }
#pragma unroll
            for (int dp = 0; dp < 4; dp++) {
                int gg   = lane >> 3;
                int drow = dp * 16 + ((gg >> 1) << 3) + (lane & 7);
                int ch   = kf * 2 + (gg & 1);
                uint32_t off = (uint32_t)drow * 128 + (uint32_t)((ch ^ (drow & 7)) << 4);
                uint32_t vh[4], vl[4];
                ldsm_x4(Vh_b + off, vh);
                ldsm_x4(Vl_b + off, vl);
#pragma unroll
                for (int j = 0; j < 2; j++) {
                    int dt = dp * 2 + j;
                    mma_bf16(o[dt], aph, &vh[2 * j]);
                    mma_bf16(o[dt], aph, &vl[2 * j]);
                    mma_bf16(o[dt], apl, &vh[2 * j]);
                }
            }
        }
        __syncthreads();   // all warps done with this KV buffer before refill
    }

    // ---- epilogue: split to bf16 hi/lo for the out-projection ----
    float inv0 = 1.f / l0;
    float inv1 = 1.f / l1;
    size_t o0 = (size_t)(b * T_ + rg0) * DIM_ + h * HD_ + (lane & 3) * 2;
    size_t o1 = (size_t)(b * T_ + rg1) * DIM_ + h * HD_ + (lane & 3) * 2;
#pragma unroll
    for (int dt = 0; dt < 8; dt++) {
        __nv_bfloat16 h0, h1, h2, h3, e0, e1, e2, e3;
        split1(o[dt][0] * inv0, h0, e0);
        split1(o[dt][1] * inv0, h1, e1);
        split1(o[dt][2] * inv1, h2, e2);
        split1(o[dt][3] * inv1, h3, e3);
        *(uint32_t*)(g_atth + o0 + dt * 8) = packbf2(h0, h1);
        *(uint32_t*)(g_attl + o0 + dt * 8) = packbf2(e0, e1);
        *(uint32_t*)(g_atth + o1 + dt * 8) = packbf2(h2, h3);
        *(uint32_t*)(g_attl + o1 + dt * 8) = packbf2(e2, e3);
    }
}

// ---------------------------------------------------------------------------
// Launcher
// ---------------------------------------------------------------------------
extern "C" void kernel_launch(void* const* d_in, const int* in_sizes, int n_in,
                              void* d_out, int out_size) {
    const float* x  = (const float*)d_in[0];
    const float* fc = (const float*)d_in[1];
    const float* fs = (const float*)d_in[2];
    const float* wq = (const float*)d_in[3];
    const float* wk = (const float*)d_in[4];
    const float* wv = (const float*)d_in[5];
    const float* wo = (const float*)d_in[6];
    float* out = (float*)d_out;

    cudaFuncSetAttribute(tc_qkv_kernel,
                         cudaFuncAttributeMaxDynamicSharedMemorySize, GEMM_SMEM_BYTES);
    cudaFuncSetAttribute(tc_out_kernel,
                         cudaFuncAttributeMaxDynamicSharedMemorySize, GEMM_SMEM_BYTES);
    cudaFuncSetAttribute(attn_mma_kernel,
                         cudaFuncAttributeMaxDynamicSharedMemorySize, ATTN_SMEM_BYTES);

    // 0) Prepass: split x; transpose+split weights (dest resolved in device code)
    split_x_kernel<<<(M_ * DIM_ / 4) / 256, 256>>>(x);
    tsplit_kernel<<<dim3(DIM_ / 32, DIM_ / 32), dim3(32, 8)>>>(wq, 0, DIM_, DIM_);
    tsplit_kernel<<<dim3(KVD_ / 32, DIM_ / 32), dim3(32, 8)>>>(wk, 1, DIM_, KVD_);
    tsplit_kernel<<<dim3(KVD_ / 32, DIM_ / 32), dim3(32, 8)>>>(wv, 2, DIM_, KVD_);
    tsplit_kernel<<<dim3(DIM_ / 32, DIM_ / 32), dim3(32, 8)>>>(wo, 3, DIM_, DIM_);

    // 1) QKV projections + fused RoPE + split (+ V transpose), pipelined
    tc_qkv_kernel<<<dim3(24, 32), 256, GEMM_SMEM_BYTES>>>(fc, fs);

    // 2) Tensor-core causal GQA flash attention, cp.async double-buffered
    attn_mma_kernel<<<dim3(T_ / 64, H_, B_), 128, ATTN_SMEM_BYTES>>>();

    // 3) Output projection, pipelined
    tc_out_kernel<<<dim3(16, 32), 256, GEMM_SMEM_BYTES>>>(out);
}